// round 9
// baseline (speedup 1.0000x reference)
#include <cuda_runtime.h>
#include <cstdint>

#define NTHREADS 512
#define SROW 132           // activation row stride (floats): 128 + 4 pad

// ---- SMEM float-offset layout (unchanged from v3) ----
#define WP1f 0             // 32 kp-rows x 256 floats (j-pair/k-pair interleaved)
#define WP2f 8192          // 64 x 256
#define WP3f 24576         // 64 x 256
#define B1f  40960
#define B2f  41088
#define B3f  41216
#define W4f  41344
#define B4f  41472         // 4 floats (1 used)
#define PPf  41476         // 64 edges x 2 half-partials
#define ATf  41604         // 64 x SROW activations
#define SMEM_FLOATS (ATf + 64 * SROW)
#define SMEM_BYTES  (SMEM_FLOATS * 4)   // 200,208 B

typedef unsigned long long ull;

// packed fp32x2 FMA (SASS FFMA2; PTX-only form)
__device__ __forceinline__ void fma2(ull &acc, ull a, ull w) {
    asm("fma.rn.f32x2 %0, %1, %2, %0;" : "+l"(acc) : "l"(a), "l"(w));
}
__device__ __forceinline__ float2 unpack2(ull v) {
    float2 r;
    asm("mov.b64 {%0, %1}, %2;" : "=f"(r.x), "=f"(r.y) : "l"(v));
    return r;
}
__device__ __forceinline__ float ex2_apx(float x) {
    float y; asm("ex2.approx.f32 %0, %1;" : "=f"(y) : "f"(x)); return y;
}
__device__ __forceinline__ float rcp_apx(float x) {
    float y; asm("rcp.approx.f32 %0, %1;" : "=f"(y) : "f"(x)); return y;
}
// tanh(x) = 1 - 2/(1+e^{2x});  2 MUFU, ~1e-7 rel err
__device__ __forceinline__ float tanh_fast(float x) {
    float e = ex2_apx(x * 2.8853900817779268f);
    return fmaf(-2.0f, rcp_apx(1.0f + e), 1.0f);
}
__device__ __forceinline__ float sigmoid_fast(float z) {
    return rcp_apx(1.0f + ex2_apx(z * -1.4426950408889634f));
}

// One layer, lane-mapped (e3, jq): 1 edge x 16 outputs per lane.
//  act : LDS.64 At[e][2kp..+1]     -> 8 distinct rows x 4 dup = 1 wavefront
//  wgt : 8x LDS.128, 4 jq-lanes read 64B contiguous, 8x dedup across e-lanes
//  accA[i]/accB[i]: k-parity-packed partials for j0 = 64jh+8i+2jq, j1 = j0+1
template<int KP>
__device__ __forceinline__ void layer_mm(const float* __restrict__ sm, int wbase,
                                         int arow, int wq,
                                         ull accA[8], ull accB[8])
{
    #pragma unroll
    for (int i = 0; i < 8; i++) { accA[i] = 0ull; accB[i] = 0ull; }

    #pragma unroll 2
    for (int kp = 0; kp < KP; kp++) {
        ull a = *(const ull*)(sm + arow + 2 * kp);
        const float* wrow = sm + wbase + kp * 256 + wq;
        #pragma unroll
        for (int i = 0; i < 8; i++) {
            ulonglong2 w = *(const ulonglong2*)(wrow + 16 * i);
            fma2(accA[i], a, w.x);
            fma2(accB[i], a, w.y);
        }
    }
}

// epilogue: tanh(acc + bias) -> At[e][j0..j0+1] (STS.64)
__device__ __forceinline__ void epi(float* __restrict__ sm, int bf,
                                    int arow, int jbase,
                                    const ull accA[8], const ull accB[8])
{
    #pragma unroll
    for (int i = 0; i < 8; i++) {
        int j0 = jbase + 8 * i;
        float2 b = *(const float2*)(sm + bf + j0);
        float2 pA = unpack2(accA[i]);
        float2 pB = unpack2(accB[i]);
        float v0 = tanh_fast(pA.x + pA.y + b.x);
        float v1 = tanh_fast(pB.x + pB.y + b.y);
        *(float2*)(sm + arow + j0) = make_float2(v0, v1);
    }
}

__global__ void __launch_bounds__(NTHREADS, 1)
gnn_mlp_v4(const float* __restrict__ EA,
           const float* __restrict__ W1, const float* __restrict__ b1,
           const float* __restrict__ W2, const float* __restrict__ b2,
           const float* __restrict__ W3, const float* __restrict__ b3,
           const float* __restrict__ W4, const float* __restrict__ b4,
           float* __restrict__ out, int E)
{
    extern __shared__ float sm[];
    const int tid  = threadIdx.x;
    const int lane = tid & 31;
    const int warp = tid >> 5;          // 0..15
    const int jh   = warp & 1;          // j-half (0: j<64, 1: j>=64)
    const int g    = warp >> 1;         // edge-group 0..7
    const int e3   = lane >> 2;         // edge within group
    const int jq   = lane & 3;          // j-quad lane
    const int eloc = g * 8 + e3;
    const int arow = ATf + eloc * SROW;
    const int wq   = 128 * jh + 4 * jq; // float offset into kp row
    const int jbase = 64 * jh + 2 * jq; // j0(i) = jbase + 8i

    // ---- one-time weight prep: d = (k>>1)*256 + (j>>1)*4 + (j&1)*2 + (k&1)
    for (int i = tid; i < 128 * 64; i += NTHREADS) {
        int j = i >> 6, k = i & 63;
        sm[WP1f + (k >> 1) * 256 + (j >> 1) * 4 + (j & 1) * 2 + (k & 1)] = W1[i];
    }
    for (int i = tid; i < 128 * 128; i += NTHREADS) {
        int j = i >> 7, k = i & 127;
        int d = (k >> 1) * 256 + (j >> 1) * 4 + (j & 1) * 2 + (k & 1);
        sm[WP2f + d] = W2[i];
        sm[WP3f + d] = W3[i];
    }
    for (int i = tid; i < 128; i += NTHREADS) {
        sm[B1f + i] = b1[i]; sm[B2f + i] = b2[i]; sm[B3f + i] = b3[i];
        sm[W4f + i] = W4[i];
    }
    if (tid == 0) sm[B4f] = b4[0];
    __syncthreads();

    const float b4s = sm[B4f];
    const int NT = (E + 63) >> 6;

    // staging map: thread covers 2 float4 cells of the 64x16 float4 tile
    const int se0 = (tid >> 4), se1 = 32 + (tid >> 4);
    const int sc  = tid & 15;

    int t = blockIdx.x;
    float4 v0 = make_float4(0.f,0.f,0.f,0.f), v1 = v0;
    if (t < NT) {
        const float4* gsrc = (const float4*)(EA + ((size_t)(t << 6) << 6));
        int tb = t << 6;
        if (tb + se0 < E) v0 = __ldg(gsrc + se0 * 16 + sc);
        if (tb + se1 < E) v1 = __ldg(gsrc + se1 * 16 + sc);
    }

    for (; t < NT; t += gridDim.x) {
        const int tbase = t << 6;

        __syncthreads();                                  // At free
        *(float4*)(sm + ATf + se0 * SROW + sc * 4) = v0;
        *(float4*)(sm + ATf + se1 * SROW + sc * 4) = v1;
        __syncthreads();

        // prefetch next tile into registers (hidden behind 3 layers)
        int tn = t + gridDim.x;
        if (tn < NT) {
            const float4* gsrc = (const float4*)(EA + ((size_t)(tn << 6) << 6));
            int tb = tn << 6;
            v0 = (tb + se0 < E) ? __ldg(gsrc + se0 * 16 + sc) : make_float4(0.f,0.f,0.f,0.f);
            v1 = (tb + se1 < E) ? __ldg(gsrc + se1 * 16 + sc) : make_float4(0.f,0.f,0.f,0.f);
        }

        ull accA[8], accB[8];

        layer_mm<32>(sm, WP1f, arow, wq, accA, accB);     // K=64
        __syncthreads();
        epi(sm, B1f, arow, jbase, accA, accB);
        __syncthreads();

        layer_mm<64>(sm, WP2f, arow, wq, accA, accB);     // K=128
        __syncthreads();
        epi(sm, B2f, arow, jbase, accA, accB);
        __syncthreads();

        layer_mm<64>(sm, WP3f, arow, wq, accA, accB);     // K=128

        // ---- head: tanh, dot with W4, reduce over jq lanes ----
        {
            float s = 0.f;
            #pragma unroll
            for (int i = 0; i < 8; i++) {
                int j0 = jbase + 8 * i;
                float2 b3v = *(const float2*)(sm + B3f + j0);
                float2 w4v = *(const float2*)(sm + W4f + j0);
                float2 pA = unpack2(accA[i]);
                float2 pB = unpack2(accB[i]);
                float t0 = tanh_fast(pA.x + pA.y + b3v.x);
                float t1 = tanh_fast(pB.x + pB.y + b3v.y);
                s = fmaf(w4v.x, t0, fmaf(w4v.y, t1, s));
            }
            // reduce over jq (lane^1, lane^2 stay within the same e3 nibble)
            s += __shfl_xor_sync(0xFFFFFFFFu, s, 1);
            s += __shfl_xor_sync(0xFFFFFFFFu, s, 2);
            if (jq == 0) sm[PPf + eloc * 2 + jh] = s;
        }
        __syncthreads();
        if (tid < 64) {
            int eg = tbase + tid;
            if (eg < E)
                out[eg] = sigmoid_fast(sm[PPf + 2 * tid] + sm[PPf + 2 * tid + 1] + b4s);
        }
    }
}

extern "C" void kernel_launch(void* const* d_in, const int* in_sizes, int n_in,
                              void* d_out, int out_size)
{
    // metadata order: x, edge_index, edge_attr, W1, b1, W2, b2, W3, b3, W4, b4
    const float* EA = (const float*)d_in[2];
    const float* W1 = (const float*)d_in[3];
    const float* b1 = (const float*)d_in[4];
    const float* W2 = (const float*)d_in[5];
    const float* b2 = (const float*)d_in[6];
    const float* W3 = (const float*)d_in[7];
    const float* b3 = (const float*)d_in[8];
    const float* W4 = (const float*)d_in[9];
    const float* b4 = (const float*)d_in[10];
    float* out = (float*)d_out;
    const int E = out_size;   // 800000

    cudaFuncSetAttribute(gnn_mlp_v4,
                         cudaFuncAttributeMaxDynamicSharedMemorySize, SMEM_BYTES);
    int nsm = 148;
    cudaDeviceGetAttribute(&nsm, cudaDevAttrMultiProcessorCount, 0);

    gnn_mlp_v4<<<nsm, NTHREADS, SMEM_BYTES>>>(
        EA, W1, b1, W2, b2, W3, b3, W4, b4, out, E);
}

// round 10
// speedup vs baseline: 3.5700x; 3.5700x over previous
#include <cuda_runtime.h>
#include <cuda_fp16.h>
#include <cstdint>

#define NTHREADS 512

// ---- dynamic smem byte offsets ----
#define A1H 0            // input  64 x 64 fp16 (hi), 128B rows, XOR-swizzled
#define A1L 8192
#define AHo 16384        // activations 64 x 128 fp16 (hi), 256B rows
#define ALo 32768
#define W1H 49152        // W1 [j=128][k=64] fp16 hi, 128B rows
#define W1L 65536
#define W2H 81920        // W2 [128][128] fp16, 256B rows
#define W2L 114688
#define W3H 147456
#define W3L 180224
#define B1F 212992       // f32 biases etc
#define B2F 213504
#define B3F 214016
#define W4F 214528
#define B4F 215040
#define PPF 215056       // 64 x 4 f32 partials
#define SMEM_BYTES 216320

// ======================= helpers =======================
__device__ __forceinline__ uint32_t smem_u32(const void* p) {
    uint32_t a;
    asm("{ .reg .u64 t; cvta.to.shared.u64 t, %1; cvt.u32.u64 %0, t; }"
        : "=r"(a) : "l"(p));
    return a;
}
__device__ __forceinline__ float ex2_apx(float x) {
    float y; asm("ex2.approx.f32 %0, %1;" : "=f"(y) : "f"(x)); return y;
}
__device__ __forceinline__ float rcp_apx(float x) {
    float y; asm("rcp.approx.f32 %0, %1;" : "=f"(y) : "f"(x)); return y;
}
__device__ __forceinline__ float tanh_fast(float x) {
    float e = ex2_apx(x * 2.8853900817779268f);       // e^{2x}
    return fmaf(-2.0f, rcp_apx(1.0f + e), 1.0f);
}
__device__ __forceinline__ float sigmoid_fast(float z) {
    return rcp_apx(1.0f + ex2_apx(z * -1.4426950408889634f));
}
__device__ __forceinline__ uint32_t pkh(half a, half b) {
    return (uint32_t)__half_as_ushort(a) | ((uint32_t)__half_as_ushort(b) << 16);
}

__device__ __forceinline__ void ldsm4(uint32_t r[4], uint32_t addr) {
    asm volatile("ldmatrix.sync.aligned.m8n8.x4.shared.b16 {%0,%1,%2,%3}, [%4];"
                 : "=r"(r[0]), "=r"(r[1]), "=r"(r[2]), "=r"(r[3]) : "r"(addr));
}
__device__ __forceinline__ void mma16816(float c[4], const uint32_t a[4],
                                         uint32_t b0, uint32_t b1) {
    asm volatile("mma.sync.aligned.m16n8k16.row.col.f32.f16.f16.f32 "
                 "{%0,%1,%2,%3}, {%4,%5,%6,%7}, {%8,%9}, {%0,%1,%2,%3};"
                 : "+f"(c[0]), "+f"(c[1]), "+f"(c[2]), "+f"(c[3])
                 : "r"(a[0]), "r"(a[1]), "r"(a[2]), "r"(a[3]), "r"(b0), "r"(b1));
}

// One layer: c[f][0..3] += (Ah+Al) @ (Wh+Wl)^T, 3-term split.
// aHb/aLb: sbase + Aoff + rowA*AROWB ; bHb/bLb: sbase + Woff + (32wn+l7)*BROWB
template<int KS, int AROWB, int BROWB>
__device__ __forceinline__ void layer_mma(uint32_t aHb, uint32_t aLb,
                                          uint32_t bHb, uint32_t bLb,
                                          int axor, int l7, int lg, int g3,
                                          float c[4][4])
{
    uint32_t ah[KS][4], al[KS][4];
    #pragma unroll
    for (int s = 0; s < KS; s++) {
        uint32_t off = ((uint32_t)((2 * s + lg) ^ axor)) << 4;
        ldsm4(ah[s], aHb + off);
        ldsm4(al[s], aLb + off);
    }
    #pragma unroll
    for (int f = 0; f < 4; f++) {
        uint32_t bhf = bHb + f * 8 * BROWB;
        uint32_t blf = bLb + f * 8 * BROWB;
        #pragma unroll
        for (int s2 = 0; s2 < KS / 2; s2++) {
            uint32_t off = ((uint32_t)((4 * s2 + g3) ^ l7)) << 4;
            uint32_t bh[4], bl[4];
            ldsm4(bh, bhf + off);
            mma16816(c[f], ah[2 * s2],     bh[0], bh[1]);
            mma16816(c[f], ah[2 * s2 + 1], bh[2], bh[3]);
            mma16816(c[f], al[2 * s2],     bh[0], bh[1]);
            mma16816(c[f], al[2 * s2 + 1], bh[2], bh[3]);
            ldsm4(bl, blf + off);
            mma16816(c[f], ah[2 * s2],     bl[0], bl[1]);
            mma16816(c[f], ah[2 * s2 + 1], bl[2], bl[3]);
        }
    }
}

// tanh(c + b) -> fp16 hi/lo into AHo/ALo (256B rows, swizzled)
__device__ __forceinline__ void epi_store(char* smem, float c[4][4], int bOff,
                                          int wm, int wn, int lane)
{
    int r  = 16 * wm + (lane >> 2);
    int cl = 2 * (lane & 3);
    #pragma unroll
    for (int f = 0; f < 4; f++) {
        int col = 32 * wn + 8 * f + cl;
        float2 b = *(const float2*)(smem + bOff + col * 4);
        float t0 = tanh_fast(c[f][0] + b.x), t1 = tanh_fast(c[f][1] + b.y);
        float t2 = tanh_fast(c[f][2] + b.x), t3 = tanh_fast(c[f][3] + b.y);
        half h0 = __float2half_rn(t0), h1 = __float2half_rn(t1);
        half h2 = __float2half_rn(t2), h3 = __float2half_rn(t3);
        uint32_t hp01 = pkh(h0, h1), hp23 = pkh(h2, h3);
        uint32_t lp01 = pkh(__float2half_rn(t0 - __half2float(h0)),
                            __float2half_rn(t1 - __half2float(h1)));
        uint32_t lp23 = pkh(__float2half_rn(t2 - __half2float(h2)),
                            __float2half_rn(t3 - __half2float(h3)));
        int ch = 4 * wn + f;
        int o1 = r * 256 + ((ch ^ (r & 7)) << 4) + cl * 2;
        int o2 = (r + 8) * 256 + ((ch ^ ((r + 8) & 7)) << 4) + cl * 2;
        *(uint32_t*)(smem + AHo + o1) = hp01;
        *(uint32_t*)(smem + ALo + o1) = lp01;
        *(uint32_t*)(smem + AHo + o2) = hp23;
        *(uint32_t*)(smem + ALo + o2) = lp23;
    }
}

__device__ __forceinline__ void wsplit(char* smem, int bH, int bL, int rowB,
                                       int j, int k, float v)
{
    half h = __float2half_rn(v);
    half l = __float2half_rn(v - __half2float(h));
    int off = j * rowB + ((((k >> 3) ^ (j & 7))) << 4) + (k & 7) * 2;
    *(half*)(smem + bH + off) = h;
    *(half*)(smem + bL + off) = l;
}

typedef unsigned long long ull;

__global__ void __launch_bounds__(NTHREADS, 1)
gnn_mma(const float* __restrict__ EA,
        const float* __restrict__ W1, const float* __restrict__ b1,
        const float* __restrict__ W2, const float* __restrict__ b2,
        const float* __restrict__ W3, const float* __restrict__ b3,
        const float* __restrict__ W4, const float* __restrict__ b4,
        float* __restrict__ out, int E)
{
    extern __shared__ char smem[];
    const uint32_t sb = smem_u32(smem);
    const int tid  = threadIdx.x;
    const int lane = tid & 31;
    const int warp = tid >> 5;
    const int wm = warp & 3, wn = warp >> 2;
    const int l7 = lane & 7, g3 = lane >> 3, lg = lane >> 4;
    const int rowA = 16 * wm + (lane & 15);
    const int axor = rowA & 7;

    // per-thread ldsm base addresses
    const uint32_t a1H = sb + A1H + rowA * 128, a1L = sb + A1L + rowA * 128;
    const uint32_t aH  = sb + AHo + rowA * 256, aL  = sb + ALo + rowA * 256;
    const uint32_t w1H = sb + W1H + (32 * wn + l7) * 128;
    const uint32_t w1L = sb + W1L + (32 * wn + l7) * 128;
    const uint32_t w2H = sb + W2H + (32 * wn + l7) * 256;
    const uint32_t w2L = sb + W2L + (32 * wn + l7) * 256;
    const uint32_t w3H = sb + W3H + (32 * wn + l7) * 256;
    const uint32_t w3L = sb + W3L + (32 * wn + l7) * 256;

    // ---- one-time weight split into smem ----
    for (int i = tid; i < 128 * 64; i += NTHREADS)
        wsplit(smem, W1H, W1L, 128, i >> 6, i & 63, W1[i]);
    for (int i = tid; i < 128 * 128; i += NTHREADS) {
        int j = i >> 7, k = i & 127;
        wsplit(smem, W2H, W2L, 256, j, k, W2[i]);
        wsplit(smem, W3H, W3L, 256, j, k, W3[i]);
    }
    for (int i = tid; i < 128; i += NTHREADS) {
        *(float*)(smem + B1F + i * 4) = b1[i];
        *(float*)(smem + B2F + i * 4) = b2[i];
        *(float*)(smem + B3F + i * 4) = b3[i];
        *(float*)(smem + W4F + i * 4) = W4[i];
    }
    if (tid == 0) *(float*)(smem + B4F) = b4[0];
    __syncthreads();
    const float b4s = *(const float*)(smem + B4F);

    const int NT = (E + 63) >> 6;
    const int se0 = tid >> 4, se1 = 32 + (tid >> 4), sc = tid & 15;

    int t = blockIdx.x;
    float4 v0 = make_float4(0.f, 0.f, 0.f, 0.f), v1 = v0;
    if (t < NT) {
        const float4* g = (const float4*)(EA + ((size_t)(t << 6) << 6));
        int tb = t << 6;
        if (tb + se0 < E) v0 = __ldg(g + se0 * 16 + sc);
        if (tb + se1 < E) v1 = __ldg(g + se1 * 16 + sc);
    }

    for (; t < NT; t += gridDim.x) {
        const int tbase = t << 6;

        // ---- stage input tile: f32 -> fp16 hi/lo, swizzled STS.64 ----
        {
            int chunkOff0 = ((sc >> 1) ^ (se0 & 7)) << 4;
            int chunkOff1 = ((sc >> 1) ^ (se1 & 7)) << 4;
            int o0 = se0 * 128 + chunkOff0 + (sc & 1) * 8;
            int o1 = se1 * 128 + chunkOff1 + (sc & 1) * 8;
            float4 vv[2] = {v0, v1};
            int oo[2] = {o0, o1};
            #pragma unroll
            for (int q = 0; q < 2; q++) {
                float4 v = vv[q];
                half hx = __float2half_rn(v.x), hy = __float2half_rn(v.y);
                half hz = __float2half_rn(v.z), hw = __float2half_rn(v.w);
                ull hi = (ull)pkh(hx, hy) | ((ull)pkh(hz, hw) << 32);
                ull lo = (ull)pkh(__float2half_rn(v.x - __half2float(hx)),
                                  __float2half_rn(v.y - __half2float(hy)))
                       | ((ull)pkh(__float2half_rn(v.z - __half2float(hz)),
                                   __float2half_rn(v.w - __half2float(hw))) << 32);
                *(ull*)(smem + A1H + oo[q]) = hi;
                *(ull*)(smem + A1L + oo[q]) = lo;
            }
        }
        __syncthreads();

        // prefetch next tile (hidden behind the whole tile body)
        int tn = t + gridDim.x;
        if (tn < NT) {
            const float4* g = (const float4*)(EA + ((size_t)(tn << 6) << 6));
            int tb = tn << 6;
            v0 = (tb + se0 < E) ? __ldg(g + se0 * 16 + sc) : make_float4(0.f,0.f,0.f,0.f);
            v1 = (tb + se1 < E) ? __ldg(g + se1 * 16 + sc) : make_float4(0.f,0.f,0.f,0.f);
        } else {
            v0 = make_float4(0.f,0.f,0.f,0.f); v1 = v0;
        }

        float c[4][4];

        // ---- layer 1 (K=64) ----
        #pragma unroll
        for (int f = 0; f < 4; f++) { c[f][0]=c[f][1]=c[f][2]=c[f][3]=0.f; }
        layer_mma<4, 128, 128>(a1H, a1L, w1H, w1L, axor, l7, lg, g3, c);
        epi_store(smem, c, B1F, wm, wn, lane);
        __syncthreads();

        // ---- layer 2 (K=128) ----
        #pragma unroll
        for (int f = 0; f < 4; f++) { c[f][0]=c[f][1]=c[f][2]=c[f][3]=0.f; }
        layer_mma<8, 256, 256>(aH, aL, w2H, w2L, axor, l7, lg, g3, c);
        __syncthreads();              // WAR: epi2 overwrites AHo/ALo
        epi_store(smem, c, B2F, wm, wn, lane);
        __syncthreads();

        // ---- layer 3 (K=128) ----
        #pragma unroll
        for (int f = 0; f < 4; f++) { c[f][0]=c[f][1]=c[f][2]=c[f][3]=0.f; }
        layer_mma<8, 256, 256>(aH, aL, w3H, w3L, axor, l7, lg, g3, c);

        // ---- head: tanh, dot W4, reduce ----
        {
            int r  = 16 * wm + (lane >> 2);
            int cl = 2 * (lane & 3);
            float p = 0.f, p8 = 0.f;
            #pragma unroll
            for (int f = 0; f < 4; f++) {
                int col = 32 * wn + 8 * f + cl;
                float2 b3v = *(const float2*)(smem + B3F + col * 4);
                float2 w4v = *(const float2*)(smem + W4F + col * 4);
                float t0 = tanh_fast(c[f][0] + b3v.x), t1 = tanh_fast(c[f][1] + b3v.y);
                float t2 = tanh_fast(c[f][2] + b3v.x), t3 = tanh_fast(c[f][3] + b3v.y);
                p  = fmaf(w4v.x, t0, fmaf(w4v.y, t1, p));
                p8 = fmaf(w4v.x, t2, fmaf(w4v.y, t3, p8));
            }
            p  += __shfl_xor_sync(0xFFFFFFFFu, p, 1);
            p  += __shfl_xor_sync(0xFFFFFFFFu, p, 2);
            p8 += __shfl_xor_sync(0xFFFFFFFFu, p8, 1);
            p8 += __shfl_xor_sync(0xFFFFFFFFu, p8, 2);
            if ((lane & 3) == 0) {
                *(float*)(smem + PPF + (r * 4 + wn) * 4)       = p;
                *(float*)(smem + PPF + ((r + 8) * 4 + wn) * 4) = p8;
            }
        }
        __syncthreads();
        if (tid < 64) {
            int eg = tbase + tid;
            if (eg < E) {
                float4 pp = *(const float4*)(smem + PPF + tid * 16);
                out[eg] = sigmoid_fast(pp.x + pp.y + pp.z + pp.w + b4s);
            }
        }
    }
}

extern "C" void kernel_launch(void* const* d_in, const int* in_sizes, int n_in,
                              void* d_out, int out_size)
{
    // metadata order: x, edge_index, edge_attr, W1, b1, W2, b2, W3, b3, W4, b4
    const float* EA = (const float*)d_in[2];
    const float* W1 = (const float*)d_in[3];
    const float* b1 = (const float*)d_in[4];
    const float* W2 = (const float*)d_in[5];
    const float* b2 = (const float*)d_in[6];
    const float* W3 = (const float*)d_in[7];
    const float* b3 = (const float*)d_in[8];
    const float* W4 = (const float*)d_in[9];
    const float* b4 = (const float*)d_in[10];
    float* out = (float*)d_out;
    const int E = out_size;   // 800000

    cudaFuncSetAttribute(gnn_mma,
                         cudaFuncAttributeMaxDynamicSharedMemorySize, SMEM_BYTES);
    int nsm = 148;
    cudaDeviceGetAttribute(&nsm, cudaDevAttrMultiProcessorCount, 0);

    gnn_mma<<<nsm, NTHREADS, SMEM_BYTES>>>(
        EA, W1, b1, W2, b2, W3, b3, W4, b4, out, E);
}

// round 11
// speedup vs baseline: 5.4958x; 1.5394x over previous
#include <cuda_runtime.h>
#include <cuda_fp16.h>
#include <cstdint>

#define NTHREADS 512

// ---- dynamic smem byte offsets ----
#define A1H 0            // input  64 x 64 fp16 (hi), 128B rows, XOR-swizzled
#define A1L 8192
#define AHo 16384        // activations 64 x 128 fp16 (hi), 256B rows
#define ALo 32768
#define W1H 49152        // W1 [j=128][k=64] fp16 hi, 128B rows
#define W1L 65536
#define W2H 81920        // W2 [128][128] fp16, 256B rows
#define W2L 114688
#define W3H 147456
#define W3L 180224
#define B1F 212992       // f32 biases etc
#define B2F 213504
#define B3F 214016
#define W4F 214528
#define B4F 215040
#define PPF 215056       // 64 x 4 f32 partials
#define SMEM_BYTES 216320

// ======================= helpers =======================
__device__ __forceinline__ uint32_t smem_u32(const void* p) {
    uint32_t a;
    asm("{ .reg .u64 t; cvta.to.shared.u64 t, %1; cvt.u32.u64 %0, t; }"
        : "=r"(a) : "l"(p));
    return a;
}
__device__ __forceinline__ float ex2_apx(float x) {
    float y; asm("ex2.approx.f32 %0, %1;" : "=f"(y) : "f"(x)); return y;
}
__device__ __forceinline__ float rcp_apx(float x) {
    float y; asm("rcp.approx.f32 %0, %1;" : "=f"(y) : "f"(x)); return y;
}
__device__ __forceinline__ float tanh_fast(float x) {
    float e = ex2_apx(x * 2.8853900817779268f);       // e^{2x}
    return fmaf(-2.0f, rcp_apx(1.0f + e), 1.0f);
}
__device__ __forceinline__ float sigmoid_fast(float z) {
    return rcp_apx(1.0f + ex2_apx(z * -1.4426950408889634f));
}
__device__ __forceinline__ uint32_t pkh(half a, half b) {
    return (uint32_t)__half_as_ushort(a) | ((uint32_t)__half_as_ushort(b) << 16);
}

__device__ __forceinline__ void ldsm4(uint32_t r[4], uint32_t addr) {
    asm volatile("ldmatrix.sync.aligned.m8n8.x4.shared.b16 {%0,%1,%2,%3}, [%4];"
                 : "=r"(r[0]), "=r"(r[1]), "=r"(r[2]), "=r"(r[3]) : "r"(addr));
}
__device__ __forceinline__ void mma16816(float c[4], const uint32_t a[4],
                                         uint32_t b0, uint32_t b1) {
    asm volatile("mma.sync.aligned.m16n8k16.row.col.f32.f16.f16.f32 "
                 "{%0,%1,%2,%3}, {%4,%5,%6,%7}, {%8,%9}, {%0,%1,%2,%3};"
                 : "+f"(c[0]), "+f"(c[1]), "+f"(c[2]), "+f"(c[3])
                 : "r"(a[0]), "r"(a[1]), "r"(a[2]), "r"(a[3]), "r"(b0), "r"(b1));
}

// One layer: c[f][0..3] += (Ah+Al) @ (Wh+Wl)^T, 3-term split.
// s2-outer / f-inner: every HMMA alternates across the 4 independent
// accumulators, so same-acc spacing is 4 instructions (breaks RAW chains).
template<int KS, int BROWB>
__device__ __forceinline__ void layer_mma(uint32_t aHb, uint32_t aLb,
                                          uint32_t bHb, uint32_t bLb,
                                          int axor, int l7, int lg, int g3,
                                          float c[4][4])
{
    #pragma unroll
    for (int s2 = 0; s2 < KS / 2; s2++) {
        uint32_t oa0 = ((uint32_t)((4 * s2 + lg) ^ axor)) << 4;
        uint32_t oa1 = ((uint32_t)((4 * s2 + 2 + lg) ^ axor)) << 4;
        uint32_t ah0[4], ah1[4], al0[4], al1[4];
        ldsm4(ah0, aHb + oa0);
        ldsm4(ah1, aHb + oa1);
        ldsm4(al0, aLb + oa0);
        ldsm4(al1, aLb + oa1);
        uint32_t ob = ((uint32_t)((4 * s2 + g3) ^ l7)) << 4;
        uint32_t bh[4][4], bl[4][4];
        #pragma unroll
        for (int f = 0; f < 4; f++) ldsm4(bh[f], bHb + f * 8 * BROWB + ob);
        #pragma unroll
        for (int f = 0; f < 4; f++) ldsm4(bl[f], bLb + f * 8 * BROWB + ob);
        #pragma unroll
        for (int f = 0; f < 4; f++) mma16816(c[f], ah0, bh[f][0], bh[f][1]);
        #pragma unroll
        for (int f = 0; f < 4; f++) mma16816(c[f], ah1, bh[f][2], bh[f][3]);
        #pragma unroll
        for (int f = 0; f < 4; f++) mma16816(c[f], al0, bh[f][0], bh[f][1]);
        #pragma unroll
        for (int f = 0; f < 4; f++) mma16816(c[f], al1, bh[f][2], bh[f][3]);
        #pragma unroll
        for (int f = 0; f < 4; f++) mma16816(c[f], ah0, bl[f][0], bl[f][1]);
        #pragma unroll
        for (int f = 0; f < 4; f++) mma16816(c[f], ah1, bl[f][2], bl[f][3]);
    }
}

// tanh(c + b) -> fp16 hi/lo into AHo/ALo (256B rows, swizzled)
__device__ __forceinline__ void epi_store(char* smem, float c[4][4], int bOff,
                                          int wm, int wn, int lane)
{
    int r  = 16 * wm + (lane >> 2);
    int cl = 2 * (lane & 3);
    #pragma unroll
    for (int f = 0; f < 4; f++) {
        int col = 32 * wn + 8 * f + cl;
        float2 b = *(const float2*)(smem + bOff + col * 4);
        float t0 = tanh_fast(c[f][0] + b.x), t1 = tanh_fast(c[f][1] + b.y);
        float t2 = tanh_fast(c[f][2] + b.x), t3 = tanh_fast(c[f][3] + b.y);
        half h0 = __float2half_rn(t0), h1 = __float2half_rn(t1);
        half h2 = __float2half_rn(t2), h3 = __float2half_rn(t3);
        uint32_t hp01 = pkh(h0, h1), hp23 = pkh(h2, h3);
        uint32_t lp01 = pkh(__float2half_rn(t0 - __half2float(h0)),
                            __float2half_rn(t1 - __half2float(h1)));
        uint32_t lp23 = pkh(__float2half_rn(t2 - __half2float(h2)),
                            __float2half_rn(t3 - __half2float(h3)));
        int ch = 4 * wn + f;
        int o1 = r * 256 + ((ch ^ (r & 7)) << 4) + cl * 2;
        int o2 = (r + 8) * 256 + ((ch ^ ((r + 8) & 7)) << 4) + cl * 2;
        *(uint32_t*)(smem + AHo + o1) = hp01;
        *(uint32_t*)(smem + ALo + o1) = lp01;
        *(uint32_t*)(smem + AHo + o2) = hp23;
        *(uint32_t*)(smem + ALo + o2) = lp23;
    }
}

__device__ __forceinline__ void wsplit(char* smem, int bH, int bL, int rowB,
                                       int j, int k, float v)
{
    half h = __float2half_rn(v);
    half l = __float2half_rn(v - __half2float(h));
    int off = j * rowB + ((((k >> 3) ^ (j & 7))) << 4) + (k & 7) * 2;
    *(half*)(smem + bH + off) = h;
    *(half*)(smem + bL + off) = l;
}

typedef unsigned long long ull;

__global__ void __launch_bounds__(NTHREADS, 1)
gnn_mma_v2(const float* __restrict__ EA,
           const float* __restrict__ W1, const float* __restrict__ b1,
           const float* __restrict__ W2, const float* __restrict__ b2,
           const float* __restrict__ W3, const float* __restrict__ b3,
           const float* __restrict__ W4, const float* __restrict__ b4,
           float* __restrict__ out, int E)
{
    extern __shared__ char smem[];
    const uint32_t sb = smem_u32(smem);
    const int tid  = threadIdx.x;
    const int lane = tid & 31;
    const int warp = tid >> 5;
    const int wm = warp & 3, wn = warp >> 2;
    const int l7 = lane & 7, g3 = lane >> 3, lg = lane >> 4;
    const int rowA = 16 * wm + (lane & 15);
    const int axor = rowA & 7;

    // per-thread ldsm base addresses
    const uint32_t a1H = sb + A1H + rowA * 128, a1L = sb + A1L + rowA * 128;
    const uint32_t aH  = sb + AHo + rowA * 256, aL  = sb + ALo + rowA * 256;
    const uint32_t w1H = sb + W1H + (32 * wn + l7) * 128;
    const uint32_t w1L = sb + W1L + (32 * wn + l7) * 128;
    const uint32_t w2H = sb + W2H + (32 * wn + l7) * 256;
    const uint32_t w2L = sb + W2L + (32 * wn + l7) * 256;
    const uint32_t w3H = sb + W3H + (32 * wn + l7) * 256;
    const uint32_t w3L = sb + W3L + (32 * wn + l7) * 256;

    // ---- one-time weight split into smem ----
    for (int i = tid; i < 128 * 64; i += NTHREADS)
        wsplit(smem, W1H, W1L, 128, i >> 6, i & 63, W1[i]);
    for (int i = tid; i < 128 * 128; i += NTHREADS) {
        int j = i >> 7, k = i & 127;
        wsplit(smem, W2H, W2L, 256, j, k, W2[i]);
        wsplit(smem, W3H, W3L, 256, j, k, W3[i]);
    }
    for (int i = tid; i < 128; i += NTHREADS) {
        *(float*)(smem + B1F + i * 4) = b1[i];
        *(float*)(smem + B2F + i * 4) = b2[i];
        *(float*)(smem + B3F + i * 4) = b3[i];
        *(float*)(smem + W4F + i * 4) = W4[i];
    }
    if (tid == 0) *(float*)(smem + B4F) = b4[0];
    __syncthreads();
    const float b4s = *(const float*)(smem + B4F);

    const int NT = (E + 63) >> 6;
    const int se0 = tid >> 4, se1 = 32 + (tid >> 4), sc = tid & 15;

    // staging: fp32 -> fp16 hi/lo, swizzled
    const int o0 = se0 * 128 + (((sc >> 1) ^ (se0 & 7)) << 4) + (sc & 1) * 8;
    const int o1 = se1 * 128 + (((sc >> 1) ^ (se1 & 7)) << 4) + (sc & 1) * 8;

    int t = blockIdx.x;
    float4 v0 = make_float4(0.f, 0.f, 0.f, 0.f), v1 = v0;
    if (t < NT) {
        const float4* g = (const float4*)(EA + ((size_t)(t << 6) << 6));
        int tb = t << 6;
        if (tb + se0 < E) v0 = __ldg(g + se0 * 16 + sc);
        if (tb + se1 < E) v1 = __ldg(g + se1 * 16 + sc);
    }

    // stage first tile
    {
        float4 vv[2] = {v0, v1};
        int oo[2] = {o0, o1};
        #pragma unroll
        for (int q = 0; q < 2; q++) {
            float4 v = vv[q];
            half hx = __float2half_rn(v.x), hy = __float2half_rn(v.y);
            half hz = __float2half_rn(v.z), hw = __float2half_rn(v.w);
            ull hi = (ull)pkh(hx, hy) | ((ull)pkh(hz, hw) << 32);
            ull lo = (ull)pkh(__float2half_rn(v.x - __half2float(hx)),
                              __float2half_rn(v.y - __half2float(hy)))
                   | ((ull)pkh(__float2half_rn(v.z - __half2float(hz)),
                               __float2half_rn(v.w - __half2float(hw))) << 32);
            *(ull*)(smem + A1H + oo[q]) = hi;
            *(ull*)(smem + A1L + oo[q]) = lo;
        }
    }
    __syncthreads();

    for (; t < NT; t += gridDim.x) {
        const int tbase = t << 6;

        // prefetch next tile (hidden behind whole tile body)
        int tn = t + gridDim.x;
        if (tn < NT) {
            const float4* g = (const float4*)(EA + ((size_t)(tn << 6) << 6));
            int tb = tn << 6;
            v0 = (tb + se0 < E) ? __ldg(g + se0 * 16 + sc) : make_float4(0.f,0.f,0.f,0.f);
            v1 = (tb + se1 < E) ? __ldg(g + se1 * 16 + sc) : make_float4(0.f,0.f,0.f,0.f);
        } else {
            v0 = make_float4(0.f,0.f,0.f,0.f); v1 = v0;
        }

        float c[4][4];

        // ---- layer 1 (K=64) ----
        #pragma unroll
        for (int f = 0; f < 4; f++) { c[f][0]=c[f][1]=c[f][2]=c[f][3]=0.f; }
        layer_mma<4, 128>(a1H, a1L, w1H, w1L, axor, l7, lg, g3, c);
        epi_store(smem, c, B1F, wm, wn, lane);
        __syncthreads();

        // ---- layer 2 (K=128) ----
        #pragma unroll
        for (int f = 0; f < 4; f++) { c[f][0]=c[f][1]=c[f][2]=c[f][3]=0.f; }
        layer_mma<8, 256>(aH, aL, w2H, w2L, axor, l7, lg, g3, c);
        __syncthreads();              // WAR: epi2 overwrites AHo/ALo
        epi_store(smem, c, B2F, wm, wn, lane);
        __syncthreads();

        // ---- layer 3 (K=128) ----
        #pragma unroll
        for (int f = 0; f < 4; f++) { c[f][0]=c[f][1]=c[f][2]=c[f][3]=0.f; }
        layer_mma<8, 256>(aH, aL, w3H, w3L, axor, l7, lg, g3, c);

        // ---- head: tanh, dot W4, reduce ----
        {
            int r  = 16 * wm + (lane >> 2);
            int cl = 2 * (lane & 3);
            float p = 0.f, p8 = 0.f;
            #pragma unroll
            for (int f = 0; f < 4; f++) {
                int col = 32 * wn + 8 * f + cl;
                float2 b3v = *(const float2*)(smem + B3F + col * 4);
                float2 w4v = *(const float2*)(smem + W4F + col * 4);
                float t0 = tanh_fast(c[f][0] + b3v.x), t1 = tanh_fast(c[f][1] + b3v.y);
                float t2 = tanh_fast(c[f][2] + b3v.x), t3 = tanh_fast(c[f][3] + b3v.y);
                p  = fmaf(w4v.x, t0, fmaf(w4v.y, t1, p));
                p8 = fmaf(w4v.x, t2, fmaf(w4v.y, t3, p8));
            }
            p  += __shfl_xor_sync(0xFFFFFFFFu, p, 1);
            p  += __shfl_xor_sync(0xFFFFFFFFu, p, 2);
            p8 += __shfl_xor_sync(0xFFFFFFFFu, p8, 1);
            p8 += __shfl_xor_sync(0xFFFFFFFFu, p8, 2);
            if ((lane & 3) == 0) {
                *(float*)(smem + PPF + (r * 4 + wn) * 4)       = p;
                *(float*)(smem + PPF + ((r + 8) * 4 + wn) * 4) = p8;
            }
        }
        __syncthreads();

        // ---- out-write + next-tile staging share one barrier window ----
        if (tid < 64) {
            int eg = tbase + tid;
            if (eg < E) {
                float4 pp = *(const float4*)(smem + PPF + tid * 16);
                out[eg] = sigmoid_fast(pp.x + pp.y + pp.z + pp.w + b4s);
            }
        }
        {
            float4 vv[2] = {v0, v1};
            int oo[2] = {o0, o1};
            #pragma unroll
            for (int q = 0; q < 2; q++) {
                float4 v = vv[q];
                half hx = __float2half_rn(v.x), hy = __float2half_rn(v.y);
                half hz = __float2half_rn(v.z), hw = __float2half_rn(v.w);
                ull hi = (ull)pkh(hx, hy) | ((ull)pkh(hz, hw) << 32);
                ull lo = (ull)pkh(__float2half_rn(v.x - __half2float(hx)),
                                  __float2half_rn(v.y - __half2float(hy)))
                       | ((ull)pkh(__float2half_rn(v.z - __half2float(hz)),
                                   __float2half_rn(v.w - __half2float(hw))) << 32);
                *(ull*)(smem + A1H + oo[q]) = hi;
                *(ull*)(smem + A1L + oo[q]) = lo;
            }
        }
        __syncthreads();
    }
}

extern "C" void kernel_launch(void* const* d_in, const int* in_sizes, int n_in,
                              void* d_out, int out_size)
{
    // metadata order: x, edge_index, edge_attr, W1, b1, W2, b2, W3, b3, W4, b4
    const float* EA = (const float*)d_in[2];
    const float* W1 = (const float*)d_in[3];
    const float* b1 = (const float*)d_in[4];
    const float* W2 = (const float*)d_in[5];
    const float* b2 = (const float*)d_in[6];
    const float* W3 = (const float*)d_in[7];
    const float* b3 = (const float*)d_in[8];
    const float* W4 = (const float*)d_in[9];
    const float* b4 = (const float*)d_in[10];
    float* out = (float*)d_out;
    const int E = out_size;   // 800000

    cudaFuncSetAttribute(gnn_mma_v2,
                         cudaFuncAttributeMaxDynamicSharedMemorySize, SMEM_BYTES);
    int nsm = 148;
    cudaDeviceGetAttribute(&nsm, cudaDevAttrMultiProcessorCount, 0);

    gnn_mma_v2<<<nsm, NTHREADS, SMEM_BYTES>>>(
        EA, W1, b1, W2, b2, W3, b3, W4, b4, out, E);
}

// round 13
// speedup vs baseline: 5.6970x; 1.0366x over previous
#include <cuda_runtime.h>
#include <cuda_fp16.h>
#include <cstdint>

#define NTHREADS 512
#define GT 32            // edges per group tile (2 groups of 8 warps per CTA)

// ---- dynamic smem byte offsets ----
#define A1H 0            // 2 groups x (32 x 128B) fp16-hi input, XOR-swizzled
#define A1L 8192
#define AHo 16384        // 2 groups x (32 x 256B) activations hi
#define ALo 32768
#define W1H 49152        // W1 [j=128][k=64] fp16 hi, 128B rows
#define W1L 65536
#define W2H 81920        // W2 [128][128] fp16, 256B rows
#define W2L 114688
#define W3H 147456
#define W3L 180224
#define B1F 212992       // f32 biases etc
#define B2F 213504
#define B3F 214016
#define W4F 214528
#define B4F 215040
#define PPF 215056       // 2 groups x 32 x 4 f32 partials (1KB)
#define SMEM_BYTES 216320

// ======================= helpers =======================
__device__ __forceinline__ uint32_t smem_u32(const void* p) {
    uint32_t a;
    asm("{ .reg .u64 t; cvta.to.shared.u64 t, %1; cvt.u32.u64 %0, t; }"
        : "=r"(a) : "l"(p));
    return a;
}
__device__ __forceinline__ float ex2_apx(float x) {
    float y; asm("ex2.approx.f32 %0, %1;" : "=f"(y) : "f"(x)); return y;
}
__device__ __forceinline__ float rcp_apx(float x) {
    float y; asm("rcp.approx.f32 %0, %1;" : "=f"(y) : "f"(x)); return y;
}
__device__ __forceinline__ float tanh_fast(float x) {
    float e = ex2_apx(x * 2.8853900817779268f);       // e^{2x}
    return fmaf(-2.0f, rcp_apx(1.0f + e), 1.0f);
}
__device__ __forceinline__ float sigmoid_fast(float z) {
    return rcp_apx(1.0f + ex2_apx(z * -1.4426950408889634f));
}
__device__ __forceinline__ uint32_t pkh(half a, half b) {
    return (uint32_t)__half_as_ushort(a) | ((uint32_t)__half_as_ushort(b) << 16);
}
__device__ __forceinline__ void grp_bar(int g) {
    asm volatile("bar.sync %0, %1;" :: "r"(g + 1), "r"(256) : "memory");
}

__device__ __forceinline__ void ldsm4(uint32_t r[4], uint32_t addr) {
    asm volatile("ldmatrix.sync.aligned.m8n8.x4.shared.b16 {%0,%1,%2,%3}, [%4];"
                 : "=r"(r[0]), "=r"(r[1]), "=r"(r[2]), "=r"(r[3]) : "r"(addr));
}
__device__ __forceinline__ void mma16816(float c[4], const uint32_t a[4],
                                         uint32_t b0, uint32_t b1) {
    asm volatile("mma.sync.aligned.m16n8k16.row.col.f32.f16.f16.f32 "
                 "{%0,%1,%2,%3}, {%4,%5,%6,%7}, {%8,%9}, {%0,%1,%2,%3};"
                 : "+f"(c[0]), "+f"(c[1]), "+f"(c[2]), "+f"(c[3])
                 : "r"(a[0]), "r"(a[1]), "r"(a[2]), "r"(a[3]), "r"(b0), "r"(b1));
}

// One layer: c[f][0..3] += (Ah+Al) @ (Wh+Wl)^T, 3-term split.
// s2-outer / f-inner: same-acc spacing 4 instructions (breaks RAW chains).
template<int KS, int BROWB>
__device__ __forceinline__ void layer_mma(uint32_t aHb, uint32_t aLb,
                                          uint32_t bHb, uint32_t bLb,
                                          int axor, int l7, int lg, int g3,
                                          float c[4][4])
{
    #pragma unroll
    for (int s2 = 0; s2 < KS / 2; s2++) {
        uint32_t oa0 = ((uint32_t)((4 * s2 + lg) ^ axor)) << 4;
        uint32_t oa1 = ((uint32_t)((4 * s2 + 2 + lg) ^ axor)) << 4;
        uint32_t ah0[4], ah1[4], al0[4], al1[4];
        ldsm4(ah0, aHb + oa0);
        ldsm4(ah1, aHb + oa1);
        ldsm4(al0, aLb + oa0);
        ldsm4(al1, aLb + oa1);
        uint32_t ob = ((uint32_t)((4 * s2 + g3) ^ l7)) << 4;
        uint32_t bh[4][4], bl[4][4];
        #pragma unroll
        for (int f = 0; f < 4; f++) ldsm4(bh[f], bHb + f * 8 * BROWB + ob);
        #pragma unroll
        for (int f = 0; f < 4; f++) ldsm4(bl[f], bLb + f * 8 * BROWB + ob);
        #pragma unroll
        for (int f = 0; f < 4; f++) mma16816(c[f], ah0, bh[f][0], bh[f][1]);
        #pragma unroll
        for (int f = 0; f < 4; f++) mma16816(c[f], ah1, bh[f][2], bh[f][3]);
        #pragma unroll
        for (int f = 0; f < 4; f++) mma16816(c[f], al0, bh[f][0], bh[f][1]);
        #pragma unroll
        for (int f = 0; f < 4; f++) mma16816(c[f], al1, bh[f][2], bh[f][3]);
        #pragma unroll
        for (int f = 0; f < 4; f++) mma16816(c[f], ah0, bl[f][0], bl[f][1]);
        #pragma unroll
        for (int f = 0; f < 4; f++) mma16816(c[f], ah1, bl[f][2], bl[f][3]);
    }
}

// tanh(c + b) -> fp16 hi/lo into group's AHo/ALo (256B rows, swizzled)
__device__ __forceinline__ void epi_store(char* smem, float c[4][4], int bOff,
                                          int aHg, int aLg, int wm, int wn, int lane)
{
    int r  = 16 * wm + (lane >> 2);        // row within 32-edge group tile
    int cl = 2 * (lane & 3);
    #pragma unroll
    for (int f = 0; f < 4; f++) {
        int col = 32 * wn + 8 * f + cl;
        float2 b = *(const float2*)(smem + bOff + col * 4);
        float t0 = tanh_fast(c[f][0] + b.x), t1 = tanh_fast(c[f][1] + b.y);
        float t2 = tanh_fast(c[f][2] + b.x), t3 = tanh_fast(c[f][3] + b.y);
        half h0 = __float2half_rn(t0), h1 = __float2half_rn(t1);
        half h2 = __float2half_rn(t2), h3 = __float2half_rn(t3);
        uint32_t hp01 = pkh(h0, h1), hp23 = pkh(h2, h3);
        uint32_t lp01 = pkh(__float2half_rn(t0 - __half2float(h0)),
                            __float2half_rn(t1 - __half2float(h1)));
        uint32_t lp23 = pkh(__float2half_rn(t2 - __half2float(h2)),
                            __float2half_rn(t3 - __half2float(h3)));
        int ch = 4 * wn + f;
        int o1 = r * 256 + ((ch ^ (r & 7)) << 4) + cl * 2;
        int o2 = (r + 8) * 256 + ((ch ^ ((r + 8) & 7)) << 4) + cl * 2;
        *(uint32_t*)(smem + aHg + o1) = hp01;
        *(uint32_t*)(smem + aLg + o1) = lp01;
        *(uint32_t*)(smem + aHg + o2) = hp23;
        *(uint32_t*)(smem + aLg + o2) = lp23;
    }
}

__device__ __forceinline__ void wsplit(char* smem, int bH, int bL, int rowB,
                                       int j, int k, float v)
{
    half h = __float2half_rn(v);
    half l = __float2half_rn(v - __half2float(h));
    int off = j * rowB + ((((k >> 3) ^ (j & 7))) << 4) + (k & 7) * 2;
    *(half*)(smem + bH + off) = h;
    *(half*)(smem + bL + off) = l;
}

typedef unsigned long long ull;

__global__ void __launch_bounds__(NTHREADS, 1)
gnn_mma_v3(const float* __restrict__ EA,
           const float* __restrict__ W1, const float* __restrict__ b1,
           const float* __restrict__ W2, const float* __restrict__ b2,
           const float* __restrict__ W3, const float* __restrict__ b3,
           const float* __restrict__ W4, const float* __restrict__ b4,
           float* __restrict__ out, int E)
{
    extern __shared__ char smem[];
    const uint32_t sb = smem_u32(smem);
    const int tid  = threadIdx.x;
    const int lane = tid & 31;
    const int warp = tid >> 5;
    const int g    = warp >> 3;            // group 0/1
    const int gw   = warp & 7;             // warp within group
    const int wm   = gw & 1, wn = gw >> 1; // 2(M) x 4(N) warp grid
    const int l7 = lane & 7, g3 = lane >> 3, lg = lane >> 4;
    const int rowA = 16 * wm + (lane & 15);
    const int axor = rowA & 7;
    const int tidg = tid & 255;            // thread within group

    // group-local buffer bases
    const int a1Hg = A1H + g * 4096, a1Lg = A1L + g * 4096;
    const int aHg  = AHo + g * 8192, aLg  = ALo + g * 8192;

    // per-thread ldsm base addresses
    const uint32_t a1H = sb + a1Hg + rowA * 128, a1L = sb + a1Lg + rowA * 128;
    const uint32_t aH  = sb + aHg  + rowA * 256, aL  = sb + aLg  + rowA * 256;
    const uint32_t w1H = sb + W1H + (32 * wn + l7) * 128;
    const uint32_t w1L = sb + W1L + (32 * wn + l7) * 128;
    const uint32_t w2H = sb + W2H + (32 * wn + l7) * 256;
    const uint32_t w2L = sb + W2L + (32 * wn + l7) * 256;
    const uint32_t w3H = sb + W3H + (32 * wn + l7) * 256;
    const uint32_t w3L = sb + W3L + (32 * wn + l7) * 256;

    // ---- one-time weight split into smem (whole CTA) ----
    for (int i = tid; i < 128 * 64; i += NTHREADS)
        wsplit(smem, W1H, W1L, 128, i >> 6, i & 63, W1[i]);
    for (int i = tid; i < 128 * 128; i += NTHREADS) {
        int j = i >> 7, k = i & 127;
        wsplit(smem, W2H, W2L, 256, j, k, W2[i]);
        wsplit(smem, W3H, W3L, 256, j, k, W3[i]);
    }
    for (int i = tid; i < 128; i += NTHREADS) {
        *(float*)(smem + B1F + i * 4) = b1[i];
        *(float*)(smem + B2F + i * 4) = b2[i];
        *(float*)(smem + B3F + i * 4) = b3[i];
        *(float*)(smem + W4F + i * 4) = W4[i];
    }
    if (tid == 0) *(float*)(smem + B4F) = b4[0];
    __syncthreads();
    const float b4s = *(const float*)(smem + B4F);

    const int NT = (E + GT - 1) >> 5;      // 32-edge tiles

    // staging map (group-local): 32 rows x 16 float4-cols, 2 cells/thread
    const int se0 = tidg >> 4, se1 = 16 + se0, sc = tidg & 15;
    const int o0 = se0 * 128 + (((sc >> 1) ^ (se0 & 7)) << 4) + (sc & 1) * 8;
    const int o1 = se1 * 128 + (((sc >> 1) ^ (se1 & 7)) << 4) + (sc & 1) * 8;

    int t = blockIdx.x * 2 + g;
    float4 v0 = make_float4(0.f, 0.f, 0.f, 0.f), v1 = v0;
    if (t < NT) {
        const float4* gp = (const float4*)(EA + ((size_t)(t * GT) << 6));
        int tb = t * GT;
        if (tb + se0 < E) v0 = __ldg(gp + se0 * 16 + sc);
        if (tb + se1 < E) v1 = __ldg(gp + se1 * 16 + sc);
    }

    // stage first tile
    {
        float4 vv[2] = {v0, v1};
        int oo[2] = {o0, o1};
        #pragma unroll
        for (int q = 0; q < 2; q++) {
            float4 v = vv[q];
            half hx = __float2half_rn(v.x), hy = __float2half_rn(v.y);
            half hz = __float2half_rn(v.z), hw = __float2half_rn(v.w);
            ull hi = (ull)pkh(hx, hy) | ((ull)pkh(hz, hw) << 32);
            ull lo = (ull)pkh(__float2half_rn(v.x - __half2float(hx)),
                              __float2half_rn(v.y - __half2float(hy)))
                   | ((ull)pkh(__float2half_rn(v.z - __half2float(hz)),
                               __float2half_rn(v.w - __half2float(hw))) << 32);
            *(ull*)(smem + a1Hg + oo[q]) = hi;
            *(ull*)(smem + a1Lg + oo[q]) = lo;
        }
    }
    grp_bar(g);

    for (; t < NT; t += gridDim.x * 2) {
        const int tbase = t * GT;

        // prefetch next tile (hidden behind whole tile body)
        int tn = t + gridDim.x * 2;
        if (tn < NT) {
            const float4* gp = (const float4*)(EA + ((size_t)(tn * GT) << 6));
            int tb = tn * GT;
            v0 = (tb + se0 < E) ? __ldg(gp + se0 * 16 + sc) : make_float4(0.f,0.f,0.f,0.f);
            v1 = (tb + se1 < E) ? __ldg(gp + se1 * 16 + sc) : make_float4(0.f,0.f,0.f,0.f);
        } else {
            v0 = make_float4(0.f,0.f,0.f,0.f); v1 = v0;
        }

        float c[4][4];

        // ---- layer 1 (K=64) ----
        #pragma unroll
        for (int f = 0; f < 4; f++) { c[f][0]=c[f][1]=c[f][2]=c[f][3]=0.f; }
        layer_mma<4, 128>(a1H, a1L, w1H, w1L, axor, l7, lg, g3, c);
        epi_store(smem, c, B1F, aHg, aLg, wm, wn, lane);
        grp_bar(g);

        // ---- layer 2 (K=128) ----
        #pragma unroll
        for (int f = 0; f < 4; f++) { c[f][0]=c[f][1]=c[f][2]=c[f][3]=0.f; }
        layer_mma<8, 256>(aH, aL, w2H, w2L, axor, l7, lg, g3, c);
        grp_bar(g);                    // WAR: epi2 overwrites AHo/ALo
        epi_store(smem, c, B2F, aHg, aLg, wm, wn, lane);
        grp_bar(g);

        // ---- layer 3 (K=128) ----
        #pragma unroll
        for (int f = 0; f < 4; f++) { c[f][0]=c[f][1]=c[f][2]=c[f][3]=0.f; }
        layer_mma<8, 256>(aH, aL, w3H, w3L, axor, l7, lg, g3, c);

        // ---- head: tanh, dot W4, reduce ----
        {
            int r  = 16 * wm + (lane >> 2);
            int cl = 2 * (lane & 3);
            float p = 0.f, p8 = 0.f;
            #pragma unroll
            for (int f = 0; f < 4; f++) {
                int col = 32 * wn + 8 * f + cl;
                float2 b3v = *(const float2*)(smem + B3F + col * 4);
                float2 w4v = *(const float2*)(smem + W4F + col * 4);
                float t0 = tanh_fast(c[f][0] + b3v.x), t1 = tanh_fast(c[f][1] + b3v.y);
                float t2 = tanh_fast(c[f][2] + b3v.x), t3 = tanh_fast(c[f][3] + b3v.y);
                p  = fmaf(w4v.x, t0, fmaf(w4v.y, t1, p));
                p8 = fmaf(w4v.x, t2, fmaf(w4v.y, t3, p8));
            }
            p  += __shfl_xor_sync(0xFFFFFFFFu, p, 1);
            p  += __shfl_xor_sync(0xFFFFFFFFu, p, 2);
            p8 += __shfl_xor_sync(0xFFFFFFFFu, p8, 1);
            p8 += __shfl_xor_sync(0xFFFFFFFFu, p8, 2);
            if ((lane & 3) == 0) {
                *(float*)(smem + PPF + ((g * 32 + r) * 4 + wn) * 4)       = p;
                *(float*)(smem + PPF + ((g * 32 + r + 8) * 4 + wn) * 4) = p8;
            }
        }
        grp_bar(g);

        // ---- out-write + next-tile staging share one barrier window ----
        if (tidg < GT) {
            int eg = tbase + tidg;
            if (eg < E) {
                float4 pp = *(const float4*)(smem + PPF + (g * 32 + tidg) * 16);
                out[eg] = sigmoid_fast(pp.x + pp.y + pp.z + pp.w + b4s);
            }
        }
        {
            float4 vv[2] = {v0, v1};
            int oo[2] = {o0, o1};
            #pragma unroll
            for (int q = 0; q < 2; q++) {
                float4 v = vv[q];
                half hx = __float2half_rn(v.x), hy = __float2half_rn(v.y);
                half hz = __float2half_rn(v.z), hw = __float2half_rn(v.w);
                ull hi = (ull)pkh(hx, hy) | ((ull)pkh(hz, hw) << 32);
                ull lo = (ull)pkh(__float2half_rn(v.x - __half2float(hx)),
                                  __float2half_rn(v.y - __half2float(hy)))
                       | ((ull)pkh(__float2half_rn(v.z - __half2float(hz)),
                                   __float2half_rn(v.w - __half2float(hw))) << 32);
                *(ull*)(smem + a1Hg + oo[q]) = hi;
                *(ull*)(smem + a1Lg + oo[q]) = lo;
            }
        }
        grp_bar(g);
    }
}

extern "C" void kernel_launch(void* const* d_in, const int* in_sizes, int n_in,
                              void* d_out, int out_size)
{
    // metadata order: x, edge_index, edge_attr, W1, b1, W2, b2, W3, b3, W4, b4
    const float* EA = (const float*)d_in[2];
    const float* W1 = (const float*)d_in[3];
    const float* b1 = (const float*)d_in[4];
    const float* W2 = (const float*)d_in[5];
    const float* b2 = (const float*)d_in[6];
    const float* W3 = (const float*)d_in[7];
    const float* b3 = (const float*)d_in[8];
    const float* W4 = (const float*)d_in[9];
    const float* b4 = (const float*)d_in[10];
    float* out = (float*)d_out;
    const int E = out_size;   // 800000

    cudaFuncSetAttribute(gnn_mma_v3,
                         cudaFuncAttributeMaxDynamicSharedMemorySize, SMEM_BYTES);
    int nsm = 148;
    cudaDeviceGetAttribute(&nsm, cudaDevAttrMultiProcessorCount, 0);

    gnn_mma_v3<<<nsm, NTHREADS, SMEM_BYTES>>>(
        EA, W1, b1, W2, b2, W3, b3, W4, b4, out, E);
}

// round 14
// speedup vs baseline: 5.8091x; 1.0197x over previous
#include <cuda_runtime.h>
#include <cuda_fp16.h>
#include <cstdint>

#define NTHREADS 512
#define GT 32            // edges per group tile (2 groups of 8 warps per CTA)

// ---- dynamic smem byte offsets ----
#define A1H 0            // 2 groups x (32 x 128B) fp16-hi input, XOR-swizzled
#define A1L 8192
#define AHo 16384        // 2 groups x (32 x 256B) activations hi
#define ALo 32768
#define W1H 49152        // W1 [j=128][k=64] fp16 hi, 128B rows
#define W1L 65536
#define W2H 81920        // W2 [128][128] fp16, 256B rows
#define W2L 114688
#define W3H 147456
#define W3L 180224
#define B1F 212992       // f32 biases etc
#define B2F 213504
#define B3F 214016
#define W4F 214528
#define B4F 215040
#define PPF 215056       // 2 groups x 32 x 4 f32 partials (1KB)
#define SMEM_BYTES 216320

// ======================= helpers =======================
__device__ __forceinline__ uint32_t smem_u32(const void* p) {
    uint32_t a;
    asm("{ .reg .u64 t; cvta.to.shared.u64 t, %1; cvt.u32.u64 %0, t; }"
        : "=r"(a) : "l"(p));
    return a;
}
__device__ __forceinline__ float ex2_apx(float x) {
    float y; asm("ex2.approx.f32 %0, %1;" : "=f"(y) : "f"(x)); return y;
}
__device__ __forceinline__ float rcp_apx(float x) {
    float y; asm("rcp.approx.f32 %0, %1;" : "=f"(y) : "f"(x)); return y;
}
__device__ __forceinline__ float tanh_fast(float x) {
    float e = ex2_apx(x * 2.8853900817779268f);       // e^{2x}
    return fmaf(-2.0f, rcp_apx(1.0f + e), 1.0f);
}
__device__ __forceinline__ float sigmoid_fast(float z) {
    return rcp_apx(1.0f + ex2_apx(z * -1.4426950408889634f));
}
__device__ __forceinline__ uint32_t pkh(half a, half b) {
    return (uint32_t)__half_as_ushort(a) | ((uint32_t)__half_as_ushort(b) << 16);
}
__device__ __forceinline__ void grp_bar(int g) {
    asm volatile("bar.sync %0, %1;" :: "r"(g + 1), "r"(256) : "memory");
}

__device__ __forceinline__ void ldsm4(uint32_t r[4], uint32_t addr) {
    asm volatile("ldmatrix.sync.aligned.m8n8.x4.shared.b16 {%0,%1,%2,%3}, [%4];"
                 : "=r"(r[0]), "=r"(r[1]), "=r"(r[2]), "=r"(r[3]) : "r"(addr));
}
__device__ __forceinline__ void mma16816(float c[4], const uint32_t a[4],
                                         uint32_t b0, uint32_t b1) {
    asm volatile("mma.sync.aligned.m16n8k16.row.col.f32.f16.f16.f32 "
                 "{%0,%1,%2,%3}, {%4,%5,%6,%7}, {%8,%9}, {%0,%1,%2,%3};"
                 : "+f"(c[0]), "+f"(c[1]), "+f"(c[2]), "+f"(c[3])
                 : "r"(a[0]), "r"(a[1]), "r"(a[2]), "r"(a[3]), "r"(b0), "r"(b1));
}

// One layer: c[f][0..3] += (Ah+Al) @ (Wh+Wl)^T, 3-term split.
// s2-outer / f-inner: same-acc spacing 4 instructions (breaks RAW chains).
template<int KS, int BROWB>
__device__ __forceinline__ void layer_mma(uint32_t aHb, uint32_t aLb,
                                          uint32_t bHb, uint32_t bLb,
                                          int axor, int l7, int lg, int g3,
                                          float c[4][4])
{
    #pragma unroll
    for (int s2 = 0; s2 < KS / 2; s2++) {
        uint32_t oa0 = ((uint32_t)((4 * s2 + lg) ^ axor)) << 4;
        uint32_t oa1 = ((uint32_t)((4 * s2 + 2 + lg) ^ axor)) << 4;
        uint32_t ah0[4], ah1[4], al0[4], al1[4];
        ldsm4(ah0, aHb + oa0);
        ldsm4(ah1, aHb + oa1);
        ldsm4(al0, aLb + oa0);
        ldsm4(al1, aLb + oa1);
        uint32_t ob = ((uint32_t)((4 * s2 + g3) ^ l7)) << 4;
        uint32_t bh[4][4], bl[4][4];
        #pragma unroll
        for (int f = 0; f < 4; f++) ldsm4(bh[f], bHb + f * 8 * BROWB + ob);
        #pragma unroll
        for (int f = 0; f < 4; f++) ldsm4(bl[f], bLb + f * 8 * BROWB + ob);
        #pragma unroll
        for (int f = 0; f < 4; f++) mma16816(c[f], ah0, bh[f][0], bh[f][1]);
        #pragma unroll
        for (int f = 0; f < 4; f++) mma16816(c[f], ah1, bh[f][2], bh[f][3]);
        #pragma unroll
        for (int f = 0; f < 4; f++) mma16816(c[f], al0, bh[f][0], bh[f][1]);
        #pragma unroll
        for (int f = 0; f < 4; f++) mma16816(c[f], al1, bh[f][2], bh[f][3]);
        #pragma unroll
        for (int f = 0; f < 4; f++) mma16816(c[f], ah0, bl[f][0], bl[f][1]);
        #pragma unroll
        for (int f = 0; f < 4; f++) mma16816(c[f], ah1, bl[f][2], bl[f][3]);
    }
}

// tanh(c + b) -> fp16 hi/lo into group's AHo/ALo (256B rows, swizzled)
__device__ __forceinline__ void epi_store(char* smem, float c[4][4], int bOff,
                                          int aHg, int aLg, int wm, int wn, int lane)
{
    int r  = 16 * wm + (lane >> 2);        // row within 32-edge group tile
    int cl = 2 * (lane & 3);
    #pragma unroll
    for (int f = 0; f < 4; f++) {
        int col = 32 * wn + 8 * f + cl;
        float2 b = *(const float2*)(smem + bOff + col * 4);
        float t0 = tanh_fast(c[f][0] + b.x), t1 = tanh_fast(c[f][1] + b.y);
        float t2 = tanh_fast(c[f][2] + b.x), t3 = tanh_fast(c[f][3] + b.y);
        half h0 = __float2half_rn(t0), h1 = __float2half_rn(t1);
        half h2 = __float2half_rn(t2), h3 = __float2half_rn(t3);
        uint32_t hp01 = pkh(h0, h1), hp23 = pkh(h2, h3);
        uint32_t lp01 = pkh(__float2half_rn(t0 - __half2float(h0)),
                            __float2half_rn(t1 - __half2float(h1)));
        uint32_t lp23 = pkh(__float2half_rn(t2 - __half2float(h2)),
                            __float2half_rn(t3 - __half2float(h3)));
        int ch = 4 * wn + f;
        int o1 = r * 256 + ((ch ^ (r & 7)) << 4) + cl * 2;
        int o2 = (r + 8) * 256 + ((ch ^ ((r + 8) & 7)) << 4) + cl * 2;
        *(uint32_t*)(smem + aHg + o1) = hp01;
        *(uint32_t*)(smem + aLg + o1) = lp01;
        *(uint32_t*)(smem + aHg + o2) = hp23;
        *(uint32_t*)(smem + aLg + o2) = lp23;
    }
}

__device__ __forceinline__ void wsplit(char* smem, int bH, int bL, int rowB,
                                       int j, int k, float v)
{
    half h = __float2half_rn(v);
    half l = __float2half_rn(v - __half2float(h));
    int off = j * rowB + ((((k >> 3) ^ (j & 7))) << 4) + (k & 7) * 2;
    *(half*)(smem + bH + off) = h;
    *(half*)(smem + bL + off) = l;
}

typedef unsigned long long ull;

__global__ void __launch_bounds__(NTHREADS, 1)
gnn_mma_v4(const float* __restrict__ EA,
           const float* __restrict__ W1, const float* __restrict__ b1,
           const float* __restrict__ W2, const float* __restrict__ b2,
           const float* __restrict__ W3, const float* __restrict__ b3,
           const float* __restrict__ W4, const float* __restrict__ b4,
           float* __restrict__ out, int E)
{
    extern __shared__ char smem[];
    const uint32_t sb = smem_u32(smem);
    const int tid  = threadIdx.x;
    const int lane = tid & 31;
    const int warp = tid >> 5;
    const int g    = warp >> 3;            // group 0/1
    const int gw   = warp & 7;             // warp within group
    const int wm   = gw & 1, wn = gw >> 1; // 2(M) x 4(N) warp grid
    const int l7 = lane & 7, g3 = lane >> 3, lg = lane >> 4;
    const int rowA = 16 * wm + (lane & 15);
    const int axor = rowA & 7;
    const int tidg = tid & 255;            // thread within group

    // group-local buffer bases
    const int a1Hg = A1H + g * 4096, a1Lg = A1L + g * 4096;
    const int aHg  = AHo + g * 8192, aLg  = ALo + g * 8192;

    // per-thread ldsm base addresses
    const uint32_t a1H = sb + a1Hg + rowA * 128, a1L = sb + a1Lg + rowA * 128;
    const uint32_t aH  = sb + aHg  + rowA * 256, aL  = sb + aLg  + rowA * 256;
    const uint32_t w1H = sb + W1H + (32 * wn + l7) * 128;
    const uint32_t w1L = sb + W1L + (32 * wn + l7) * 128;
    const uint32_t w2H = sb + W2H + (32 * wn + l7) * 256;
    const uint32_t w2L = sb + W2L + (32 * wn + l7) * 256;
    const uint32_t w3H = sb + W3H + (32 * wn + l7) * 256;
    const uint32_t w3L = sb + W3L + (32 * wn + l7) * 256;

    // ---- one-time weight split into smem (whole CTA) ----
    for (int i = tid; i < 128 * 64; i += NTHREADS)
        wsplit(smem, W1H, W1L, 128, i >> 6, i & 63, W1[i]);
    for (int i = tid; i < 128 * 128; i += NTHREADS) {
        int j = i >> 7, k = i & 127;
        wsplit(smem, W2H, W2L, 256, j, k, W2[i]);
        wsplit(smem, W3H, W3L, 256, j, k, W3[i]);
    }
    for (int i = tid; i < 128; i += NTHREADS) {
        *(float*)(smem + B1F + i * 4) = b1[i];
        *(float*)(smem + B2F + i * 4) = b2[i];
        *(float*)(smem + B3F + i * 4) = b3[i];
        *(float*)(smem + W4F + i * 4) = W4[i];
    }
    if (tid == 0) *(float*)(smem + B4F) = b4[0];
    __syncthreads();
    const float b4s = *(const float*)(smem + B4F);

    const int NT = (E + GT - 1) >> 5;      // 32-edge tiles

    // staging map (group-local): 32 rows x 16 float4-cols, 2 cells/thread
    const int se0 = tidg >> 4, se1 = 16 + se0, sc = tidg & 15;
    const int o0 = se0 * 128 + (((sc >> 1) ^ (se0 & 7)) << 4) + (sc & 1) * 8;
    const int o1 = se1 * 128 + (((sc >> 1) ^ (se1 & 7)) << 4) + (sc & 1) * 8;

    int t = blockIdx.x * 2 + g;
    float4 v0 = make_float4(0.f, 0.f, 0.f, 0.f), v1 = v0;
    if (t < NT) {
        const float4* gp = (const float4*)(EA + ((size_t)(t * GT) << 6));
        int tb = t * GT;
        if (tb + se0 < E) v0 = __ldg(gp + se0 * 16 + sc);
        if (tb + se1 < E) v1 = __ldg(gp + se1 * 16 + sc);
    }

    // stage first tile
    {
        float4 vv[2] = {v0, v1};
        int oo[2] = {o0, o1};
        #pragma unroll
        for (int q = 0; q < 2; q++) {
            float4 v = vv[q];
            half hx = __float2half_rn(v.x), hy = __float2half_rn(v.y);
            half hz = __float2half_rn(v.z), hw = __float2half_rn(v.w);
            ull hi = (ull)pkh(hx, hy) | ((ull)pkh(hz, hw) << 32);
            ull lo = (ull)pkh(__float2half_rn(v.x - __half2float(hx)),
                              __float2half_rn(v.y - __half2float(hy)))
                   | ((ull)pkh(__float2half_rn(v.z - __half2float(hz)),
                               __float2half_rn(v.w - __half2float(hw))) << 32);
            *(ull*)(smem + a1Hg + oo[q]) = hi;
            *(ull*)(smem + a1Lg + oo[q]) = lo;
        }
    }
    grp_bar(g);

    // ---- PHASE STAGGER: group 1 runs an idempotent L1+epi1 / L2+epi2
    // warm-up on its first tile (~half a tile body). All warm-up smem writes
    // are warp-partitioned and rewritten with identical values by the main
    // loop, so results are unchanged; the two groups end up anti-phase and
    // stay there (no coupling re-locks them).
    if (g == 1 && t < NT) {
        float c[4][4];
        #pragma unroll
        for (int f = 0; f < 4; f++) { c[f][0]=c[f][1]=c[f][2]=c[f][3]=0.f; }
        layer_mma<4, 128>(a1H, a1L, w1H, w1L, axor, l7, lg, g3, c);
        epi_store(smem, c, B1F, aHg, aLg, wm, wn, lane);
        grp_bar(g);
        #pragma unroll
        for (int f = 0; f < 4; f++) { c[f][0]=c[f][1]=c[f][2]=c[f][3]=0.f; }
        layer_mma<8, 256>(aH, aL, w2H, w2L, axor, l7, lg, g3, c);
        grp_bar(g);
        epi_store(smem, c, B2F, aHg, aLg, wm, wn, lane);
        grp_bar(g);
    }

    for (; t < NT; t += gridDim.x * 2) {
        const int tbase = t * GT;

        // prefetch next tile (hidden behind whole tile body)
        int tn = t + gridDim.x * 2;
        if (tn < NT) {
            const float4* gp = (const float4*)(EA + ((size_t)(tn * GT) << 6));
            int tb = tn * GT;
            v0 = (tb + se0 < E) ? __ldg(gp + se0 * 16 + sc) : make_float4(0.f,0.f,0.f,0.f);
            v1 = (tb + se1 < E) ? __ldg(gp + se1 * 16 + sc) : make_float4(0.f,0.f,0.f,0.f);
        } else {
            v0 = make_float4(0.f,0.f,0.f,0.f); v1 = v0;
        }

        float c[4][4];

        // ---- layer 1 (K=64) ----
        #pragma unroll
        for (int f = 0; f < 4; f++) { c[f][0]=c[f][1]=c[f][2]=c[f][3]=0.f; }
        layer_mma<4, 128>(a1H, a1L, w1H, w1L, axor, l7, lg, g3, c);
        epi_store(smem, c, B1F, aHg, aLg, wm, wn, lane);
        grp_bar(g);

        // ---- layer 2 (K=128) ----
        #pragma unroll
        for (int f = 0; f < 4; f++) { c[f][0]=c[f][1]=c[f][2]=c[f][3]=0.f; }
        layer_mma<8, 256>(aH, aL, w2H, w2L, axor, l7, lg, g3, c);
        grp_bar(g);                    // WAR: epi2 overwrites AHo/ALo
        epi_store(smem, c, B2F, aHg, aLg, wm, wn, lane);
        grp_bar(g);

        // ---- layer 3 (K=128) ----
        #pragma unroll
        for (int f = 0; f < 4; f++) { c[f][0]=c[f][1]=c[f][2]=c[f][3]=0.f; }
        layer_mma<8, 256>(aH, aL, w3H, w3L, axor, l7, lg, g3, c);

        // ---- head: tanh, dot W4, reduce ----
        {
            int r  = 16 * wm + (lane >> 2);
            int cl = 2 * (lane & 3);
            float p = 0.f, p8 = 0.f;
            #pragma unroll
            for (int f = 0; f < 4; f++) {
                int col = 32 * wn + 8 * f + cl;
                float2 b3v = *(const float2*)(smem + B3F + col * 4);
                float2 w4v = *(const float2*)(smem + W4F + col * 4);
                float t0 = tanh_fast(c[f][0] + b3v.x), t1 = tanh_fast(c[f][1] + b3v.y);
                float t2 = tanh_fast(c[f][2] + b3v.x), t3 = tanh_fast(c[f][3] + b3v.y);
                p  = fmaf(w4v.x, t0, fmaf(w4v.y, t1, p));
                p8 = fmaf(w4v.x, t2, fmaf(w4v.y, t3, p8));
            }
            p  += __shfl_xor_sync(0xFFFFFFFFu, p, 1);
            p  += __shfl_xor_sync(0xFFFFFFFFu, p, 2);
            p8 += __shfl_xor_sync(0xFFFFFFFFu, p8, 1);
            p8 += __shfl_xor_sync(0xFFFFFFFFu, p8, 2);
            if ((lane & 3) == 0) {
                *(float*)(smem + PPF + ((g * 32 + r) * 4 + wn) * 4)       = p;
                *(float*)(smem + PPF + ((g * 32 + r + 8) * 4 + wn) * 4) = p8;
            }
        }
        grp_bar(g);

        // ---- out-write + next-tile staging share one barrier window ----
        if (tidg < GT) {
            int eg = tbase + tidg;
            if (eg < E) {
                float4 pp = *(const float4*)(smem + PPF + (g * 32 + tidg) * 16);
                out[eg] = sigmoid_fast(pp.x + pp.y + pp.z + pp.w + b4s);
            }
        }
        {
            float4 vv[2] = {v0, v1};
            int oo[2] = {o0, o1};
            #pragma unroll
            for (int q = 0; q < 2; q++) {
                float4 v = vv[q];
                half hx = __float2half_rn(v.x), hy = __float2half_rn(v.y);
                half hz = __float2half_rn(v.z), hw = __float2half_rn(v.w);
                ull hi = (ull)pkh(hx, hy) | ((ull)pkh(hz, hw) << 32);
                ull lo = (ull)pkh(__float2half_rn(v.x - __half2float(hx)),
                                  __float2half_rn(v.y - __half2float(hy)))
                       | ((ull)pkh(__float2half_rn(v.z - __half2float(hz)),
                                   __float2half_rn(v.w - __half2float(hw))) << 32);
                *(ull*)(smem + a1Hg + oo[q]) = hi;
                *(ull*)(smem + a1Lg + oo[q]) = lo;
            }
        }
        grp_bar(g);
    }
}

extern "C" void kernel_launch(void* const* d_in, const int* in_sizes, int n_in,
                              void* d_out, int out_size)
{
    // metadata order: x, edge_index, edge_attr, W1, b1, W2, b2, W3, b3, W4, b4
    const float* EA = (const float*)d_in[2];
    const float* W1 = (const float*)d_in[3];
    const float* b1 = (const float*)d_in[4];
    const float* W2 = (const float*)d_in[5];
    const float* b2 = (const float*)d_in[6];
    const float* W3 = (const float*)d_in[7];
    const float* b3 = (const float*)d_in[8];
    const float* W4 = (const float*)d_in[9];
    const float* b4 = (const float*)d_in[10];
    float* out = (float*)d_out;
    const int E = out_size;   // 800000

    cudaFuncSetAttribute(gnn_mma_v4,
                         cudaFuncAttributeMaxDynamicSharedMemorySize, SMEM_BYTES);
    int nsm = 148;
    cudaDeviceGetAttribute(&nsm, cudaDevAttrMultiProcessorCount, 0);

    gnn_mma_v4<<<nsm, NTHREADS, SMEM_BYTES>>>(
        EA, W1, b1, W2, b2, W3, b3, W4, b4, out, E);
}

// round 15
// speedup vs baseline: 7.1595x; 1.2325x over previous
#include <cuda_runtime.h>
#include <cuda_fp16.h>
#include <cstdint>

#define NTHREADS 512
#define GT 32            // edges per group tile (2 groups of 8 warps per CTA)

// ---- dynamic smem byte offsets ----
#define A1H 0            // 2 groups x (32 x 128B) fp16-hi input, XOR-swizzled
#define A1L 8192
#define AHo 16384        // 2 groups x (32 x 256B) activations hi
#define ALo 32768
#define W1H 49152        // W1 [j=128][k=64] fp16, 128B rows (16KB)
#define W2H 65536        // W2 [128][128] fp16, 256B rows (32KB)
#define W3H 98304        // (32KB)
#define B1F 131072       // f32 biases etc
#define B2F 131584
#define B3F 132096
#define W4F 132608
#define B4F 133120
#define PPF 133136       // 2 groups x 32 x 4 f32 partials (1KB)
#define SMEM_BYTES 135168

// ======================= helpers =======================
__device__ __forceinline__ uint32_t smem_u32(const void* p) {
    uint32_t a;
    asm("{ .reg .u64 t; cvta.to.shared.u64 t, %1; cvt.u32.u64 %0, t; }"
        : "=r"(a) : "l"(p));
    return a;
}
__device__ __forceinline__ float ex2_apx(float x) {
    float y; asm("ex2.approx.f32 %0, %1;" : "=f"(y) : "f"(x)); return y;
}
__device__ __forceinline__ float rcp_apx(float x) {
    float y; asm("rcp.approx.f32 %0, %1;" : "=f"(y) : "f"(x)); return y;
}
__device__ __forceinline__ float tanh_fast(float x) {
    float e = ex2_apx(x * 2.8853900817779268f);       // e^{2x}
    return fmaf(-2.0f, rcp_apx(1.0f + e), 1.0f);
}
__device__ __forceinline__ float sigmoid_fast(float z) {
    return rcp_apx(1.0f + ex2_apx(z * -1.4426950408889634f));
}
__device__ __forceinline__ uint32_t pkh(half a, half b) {
    return (uint32_t)__half_as_ushort(a) | ((uint32_t)__half_as_ushort(b) << 16);
}
__device__ __forceinline__ void grp_bar(int g) {
    asm volatile("bar.sync %0, %1;" :: "r"(g + 1), "r"(256) : "memory");
}

__device__ __forceinline__ void ldsm4(uint32_t r[4], uint32_t addr) {
    asm volatile("ldmatrix.sync.aligned.m8n8.x4.shared.b16 {%0,%1,%2,%3}, [%4];"
                 : "=r"(r[0]), "=r"(r[1]), "=r"(r[2]), "=r"(r[3]) : "r"(addr));
}
__device__ __forceinline__ void mma16816(float c[4], const uint32_t a[4],
                                         uint32_t b0, uint32_t b1) {
    asm volatile("mma.sync.aligned.m16n8k16.row.col.f32.f16.f16.f32 "
                 "{%0,%1,%2,%3}, {%4,%5,%6,%7}, {%8,%9}, {%0,%1,%2,%3};"
                 : "+f"(c[0]), "+f"(c[1]), "+f"(c[2]), "+f"(c[3])
                 : "r"(a[0]), "r"(a[1]), "r"(a[2]), "r"(a[3]), "r"(b0), "r"(b1));
}

// One layer: c[f][0..3] += (Ah + Al) @ Wh^T  (2-term split: fp16 weights,
// hi/lo-split activations). s2-outer / f-inner keeps same-acc spacing at 4.
template<int KS, int BROWB>
__device__ __forceinline__ void layer_mma(uint32_t aHb, uint32_t aLb,
                                          uint32_t bHb,
                                          int axor, int l7, int lg, int g3,
                                          float c[4][4])
{
    #pragma unroll
    for (int s2 = 0; s2 < KS / 2; s2++) {
        uint32_t oa0 = ((uint32_t)((4 * s2 + lg) ^ axor)) << 4;
        uint32_t oa1 = ((uint32_t)((4 * s2 + 2 + lg) ^ axor)) << 4;
        uint32_t ah0[4], ah1[4], al0[4], al1[4];
        ldsm4(ah0, aHb + oa0);
        ldsm4(ah1, aHb + oa1);
        ldsm4(al0, aLb + oa0);
        ldsm4(al1, aLb + oa1);
        uint32_t ob = ((uint32_t)((4 * s2 + g3) ^ l7)) << 4;
        uint32_t bh[4][4];
        #pragma unroll
        for (int f = 0; f < 4; f++) ldsm4(bh[f], bHb + f * 8 * BROWB + ob);
        #pragma unroll
        for (int f = 0; f < 4; f++) mma16816(c[f], ah0, bh[f][0], bh[f][1]);
        #pragma unroll
        for (int f = 0; f < 4; f++) mma16816(c[f], ah1, bh[f][2], bh[f][3]);
        #pragma unroll
        for (int f = 0; f < 4; f++) mma16816(c[f], al0, bh[f][0], bh[f][1]);
        #pragma unroll
        for (int f = 0; f < 4; f++) mma16816(c[f], al1, bh[f][2], bh[f][3]);
    }
}

// tanh(c + b) -> fp16 hi/lo into group's AHo/ALo (256B rows, swizzled)
__device__ __forceinline__ void epi_store(char* smem, float c[4][4], int bOff,
                                          int aHg, int aLg, int wm, int wn, int lane)
{
    int r  = 16 * wm + (lane >> 2);        // row within 32-edge group tile
    int cl = 2 * (lane & 3);
    #pragma unroll
    for (int f = 0; f < 4; f++) {
        int col = 32 * wn + 8 * f + cl;
        float2 b = *(const float2*)(smem + bOff + col * 4);
        float t0 = tanh_fast(c[f][0] + b.x), t1 = tanh_fast(c[f][1] + b.y);
        float t2 = tanh_fast(c[f][2] + b.x), t3 = tanh_fast(c[f][3] + b.y);
        half h0 = __float2half_rn(t0), h1 = __float2half_rn(t1);
        half h2 = __float2half_rn(t2), h3 = __float2half_rn(t3);
        uint32_t hp01 = pkh(h0, h1), hp23 = pkh(h2, h3);
        uint32_t lp01 = pkh(__float2half_rn(t0 - __half2float(h0)),
                            __float2half_rn(t1 - __half2float(h1)));
        uint32_t lp23 = pkh(__float2half_rn(t2 - __half2float(h2)),
                            __float2half_rn(t3 - __half2float(h3)));
        int ch = 4 * wn + f;
        int o1 = r * 256 + ((ch ^ (r & 7)) << 4) + cl * 2;
        int o2 = (r + 8) * 256 + ((ch ^ ((r + 8) & 7)) << 4) + cl * 2;
        *(uint32_t*)(smem + aHg + o1) = hp01;
        *(uint32_t*)(smem + aLg + o1) = lp01;
        *(uint32_t*)(smem + aHg + o2) = hp23;
        *(uint32_t*)(smem + aLg + o2) = lp23;
    }
}

// weights: plain fp16 (no residual), SW-swizzled rows
__device__ __forceinline__ void wstore(char* smem, int bH, int rowB,
                                       int j, int k, float v)
{
    int off = j * rowB + ((((k >> 3) ^ (j & 7))) << 4) + (k & 7) * 2;
    *(half*)(smem + bH + off) = __float2half_rn(v);
}

typedef unsigned long long ull;

__global__ void __launch_bounds__(NTHREADS, 1)
gnn_mma_v5(const float* __restrict__ EA,
           const float* __restrict__ W1, const float* __restrict__ b1,
           const float* __restrict__ W2, const float* __restrict__ b2,
           const float* __restrict__ W3, const float* __restrict__ b3,
           const float* __restrict__ W4, const float* __restrict__ b4,
           float* __restrict__ out, int E)
{
    extern __shared__ char smem[];
    const uint32_t sb = smem_u32(smem);
    const int tid  = threadIdx.x;
    const int lane = tid & 31;
    const int warp = tid >> 5;
    const int g    = warp >> 3;            // group 0/1
    const int gw   = warp & 7;             // warp within group
    const int wm   = gw & 1, wn = gw >> 1; // 2(M) x 4(N) warp grid
    const int l7 = lane & 7, g3 = lane >> 3, lg = lane >> 4;
    const int rowA = 16 * wm + (lane & 15);
    const int axor = rowA & 7;
    const int tidg = tid & 255;            // thread within group

    // group-local buffer bases
    const int a1Hg = A1H + g * 4096, a1Lg = A1L + g * 4096;
    const int aHg  = AHo + g * 8192, aLg  = ALo + g * 8192;

    // per-thread ldsm base addresses
    const uint32_t a1H = sb + a1Hg + rowA * 128, a1L = sb + a1Lg + rowA * 128;
    const uint32_t aH  = sb + aHg  + rowA * 256, aL  = sb + aLg  + rowA * 256;
    const uint32_t w1H = sb + W1H + (32 * wn + l7) * 128;
    const uint32_t w2H = sb + W2H + (32 * wn + l7) * 256;
    const uint32_t w3H = sb + W3H + (32 * wn + l7) * 256;

    // ---- one-time weight store into smem (whole CTA) ----
    for (int i = tid; i < 128 * 64; i += NTHREADS)
        wstore(smem, W1H, 128, i >> 6, i & 63, W1[i]);
    for (int i = tid; i < 128 * 128; i += NTHREADS) {
        int j = i >> 7, k = i & 127;
        wstore(smem, W2H, 256, j, k, W2[i]);
        wstore(smem, W3H, 256, j, k, W3[i]);
    }
    for (int i = tid; i < 128; i += NTHREADS) {
        *(float*)(smem + B1F + i * 4) = b1[i];
        *(float*)(smem + B2F + i * 4) = b2[i];
        *(float*)(smem + B3F + i * 4) = b3[i];
        *(float*)(smem + W4F + i * 4) = W4[i];
    }
    if (tid == 0) *(float*)(smem + B4F) = b4[0];
    __syncthreads();
    const float b4s = *(const float*)(smem + B4F);

    const int NT = (E + GT - 1) >> 5;      // 32-edge tiles

    // staging map (group-local): 32 rows x 16 float4-cols, 2 cells/thread
    const int se0 = tidg >> 4, se1 = 16 + se0, sc = tidg & 15;
    const int o0 = se0 * 128 + (((sc >> 1) ^ (se0 & 7)) << 4) + (sc & 1) * 8;
    const int o1 = se1 * 128 + (((sc >> 1) ^ (se1 & 7)) << 4) + (sc & 1) * 8;

    int t = blockIdx.x * 2 + g;
    float4 v0 = make_float4(0.f, 0.f, 0.f, 0.f), v1 = v0;
    if (t < NT) {
        const float4* gp = (const float4*)(EA + ((size_t)(t * GT) << 6));
        int tb = t * GT;
        if (tb + se0 < E) v0 = __ldg(gp + se0 * 16 + sc);
        if (tb + se1 < E) v1 = __ldg(gp + se1 * 16 + sc);
    }

    // stage first tile
    {
        float4 vv[2] = {v0, v1};
        int oo[2] = {o0, o1};
        #pragma unroll
        for (int q = 0; q < 2; q++) {
            float4 v = vv[q];
            half hx = __float2half_rn(v.x), hy = __float2half_rn(v.y);
            half hz = __float2half_rn(v.z), hw = __float2half_rn(v.w);
            ull hi = (ull)pkh(hx, hy) | ((ull)pkh(hz, hw) << 32);
            ull lo = (ull)pkh(__float2half_rn(v.x - __half2float(hx)),
                              __float2half_rn(v.y - __half2float(hy)))
                   | ((ull)pkh(__float2half_rn(v.z - __half2float(hz)),
                               __float2half_rn(v.w - __half2float(hw))) << 32);
            *(ull*)(smem + a1Hg + oo[q]) = hi;
            *(ull*)(smem + a1Lg + oo[q]) = lo;
        }
    }
    grp_bar(g);

    // ---- PHASE STAGGER (kept from v4): group 1 runs an idempotent
    // L1+epi1 / L2+epi2 warm-up on its first tile.
    if (g == 1 && t < NT) {
        float c[4][4];
        #pragma unroll
        for (int f = 0; f < 4; f++) { c[f][0]=c[f][1]=c[f][2]=c[f][3]=0.f; }
        layer_mma<4, 128>(a1H, a1L, w1H, axor, l7, lg, g3, c);
        epi_store(smem, c, B1F, aHg, aLg, wm, wn, lane);
        grp_bar(g);
        #pragma unroll
        for (int f = 0; f < 4; f++) { c[f][0]=c[f][1]=c[f][2]=c[f][3]=0.f; }
        layer_mma<8, 256>(aH, aL, w2H, axor, l7, lg, g3, c);
        grp_bar(g);
        epi_store(smem, c, B2F, aHg, aLg, wm, wn, lane);
        grp_bar(g);
    }

    for (; t < NT; t += gridDim.x * 2) {
        const int tbase = t * GT;

        // prefetch next tile (hidden behind whole tile body)
        int tn = t + gridDim.x * 2;
        if (tn < NT) {
            const float4* gp = (const float4*)(EA + ((size_t)(tn * GT) << 6));
            int tb = tn * GT;
            v0 = (tb + se0 < E) ? __ldg(gp + se0 * 16 + sc) : make_float4(0.f,0.f,0.f,0.f);
            v1 = (tb + se1 < E) ? __ldg(gp + se1 * 16 + sc) : make_float4(0.f,0.f,0.f,0.f);
        } else {
            v0 = make_float4(0.f,0.f,0.f,0.f); v1 = v0;
        }

        float c[4][4];

        // ---- layer 1 (K=64) ----
        #pragma unroll
        for (int f = 0; f < 4; f++) { c[f][0]=c[f][1]=c[f][2]=c[f][3]=0.f; }
        layer_mma<4, 128>(a1H, a1L, w1H, axor, l7, lg, g3, c);
        epi_store(smem, c, B1F, aHg, aLg, wm, wn, lane);
        grp_bar(g);

        // ---- layer 2 (K=128) ----
        #pragma unroll
        for (int f = 0; f < 4; f++) { c[f][0]=c[f][1]=c[f][2]=c[f][3]=0.f; }
        layer_mma<8, 256>(aH, aL, w2H, axor, l7, lg, g3, c);
        grp_bar(g);                    // WAR: epi2 overwrites AHo/ALo
        epi_store(smem, c, B2F, aHg, aLg, wm, wn, lane);
        grp_bar(g);

        // ---- layer 3 (K=128) ----
        #pragma unroll
        for (int f = 0; f < 4; f++) { c[f][0]=c[f][1]=c[f][2]=c[f][3]=0.f; }
        layer_mma<8, 256>(aH, aL, w3H, axor, l7, lg, g3, c);

        // ---- head: tanh, dot W4, reduce ----
        {
            int r  = 16 * wm + (lane >> 2);
            int cl = 2 * (lane & 3);
            float p = 0.f, p8 = 0.f;
            #pragma unroll
            for (int f = 0; f < 4; f++) {
                int col = 32 * wn + 8 * f + cl;
                float2 b3v = *(const float2*)(smem + B3F + col * 4);
                float2 w4v = *(const float2*)(smem + W4F + col * 4);
                float t0 = tanh_fast(c[f][0] + b3v.x), t1 = tanh_fast(c[f][1] + b3v.y);
                float t2 = tanh_fast(c[f][2] + b3v.x), t3 = tanh_fast(c[f][3] + b3v.y);
                p  = fmaf(w4v.x, t0, fmaf(w4v.y, t1, p));
                p8 = fmaf(w4v.x, t2, fmaf(w4v.y, t3, p8));
            }
            p  += __shfl_xor_sync(0xFFFFFFFFu, p, 1);
            p  += __shfl_xor_sync(0xFFFFFFFFu, p, 2);
            p8 += __shfl_xor_sync(0xFFFFFFFFu, p8, 1);
            p8 += __shfl_xor_sync(0xFFFFFFFFu, p8, 2);
            if ((lane & 3) == 0) {
                *(float*)(smem + PPF + ((g * 32 + r) * 4 + wn) * 4)       = p;
                *(float*)(smem + PPF + ((g * 32 + r + 8) * 4 + wn) * 4) = p8;
            }
        }
        grp_bar(g);

        // ---- out-write + next-tile staging share one barrier window ----
        if (tidg < GT) {
            int eg = tbase + tidg;
            if (eg < E) {
                float4 pp = *(const float4*)(smem + PPF + (g * 32 + tidg) * 16);
                out[eg] = sigmoid_fast(pp.x + pp.y + pp.z + pp.w + b4s);
            }
        }
        {
            float4 vv[2] = {v0, v1};
            int oo[2] = {o0, o1};
            #pragma unroll
            for (int q = 0; q < 2; q++) {
                float4 v = vv[q];
                half hx = __float2half_rn(v.x), hy = __float2half_rn(v.y);
                half hz = __float2half_rn(v.z), hw = __float2half_rn(v.w);
                ull hi = (ull)pkh(hx, hy) | ((ull)pkh(hz, hw) << 32);
                ull lo = (ull)pkh(__float2half_rn(v.x - __half2float(hx)),
                                  __float2half_rn(v.y - __half2float(hy)))
                       | ((ull)pkh(__float2half_rn(v.z - __half2float(hz)),
                                   __float2half_rn(v.w - __half2float(hw))) << 32);
                *(ull*)(smem + a1Hg + oo[q]) = hi;
                *(ull*)(smem + a1Lg + oo[q]) = lo;
            }
        }
        grp_bar(g);
    }
}

extern "C" void kernel_launch(void* const* d_in, const int* in_sizes, int n_in,
                              void* d_out, int out_size)
{
    // metadata order: x, edge_index, edge_attr, W1, b1, W2, b2, W3, b3, W4, b4
    const float* EA = (const float*)d_in[2];
    const float* W1 = (const float*)d_in[3];
    const float* b1 = (const float*)d_in[4];
    const float* W2 = (const float*)d_in[5];
    const float* b2 = (const float*)d_in[6];
    const float* W3 = (const float*)d_in[7];
    const float* b3 = (const float*)d_in[8];
    const float* W4 = (const float*)d_in[9];
    const float* b4 = (const float*)d_in[10];
    float* out = (float*)d_out;
    const int E = out_size;   // 800000

    cudaFuncSetAttribute(gnn_mma_v5,
                         cudaFuncAttributeMaxDynamicSharedMemorySize, SMEM_BYTES);
    int nsm = 148;
    cudaDeviceGetAttribute(&nsm, cudaDevAttrMultiProcessorCount, 0);

    gnn_mma_v5<<<nsm, NTHREADS, SMEM_BYTES>>>(
        EA, W1, b1, W2, b2, W3, b3, W4, b4, out, E);
}

// round 16
// speedup vs baseline: 9.9439x; 1.3889x over previous
#include <cuda_runtime.h>
#include <cuda_fp16.h>
#include <cstdint>

#define NTHREADS 512
#define GT 32            // edges per group tile (2 groups of 8 warps per CTA)

// ---- dynamic smem byte offsets ----
#define A1H 0            // 2 groups x (32 x 128B) fp16 input, XOR-swizzled
#define AHo 8192         // 2 groups x (32 x 256B) activations fp16
#define W1H 24576        // W1 [j=128][k=64] fp16, 128B rows (16KB)
#define W2H 40960        // W2 [128][128] fp16, 256B rows (32KB)
#define W3H 73728        // (32KB)
#define B1F 106496       // f32 biases etc
#define B2F 107008
#define B3F 107520
#define W4F 108032
#define B4F 108544
#define PPF 108560       // 2 groups x 32 x 4 f32 partials (1KB)
#define SMEM_BYTES 110592

// ======================= helpers =======================
__device__ __forceinline__ uint32_t smem_u32(const void* p) {
    uint32_t a;
    asm("{ .reg .u64 t; cvta.to.shared.u64 t, %1; cvt.u32.u64 %0, t; }"
        : "=r"(a) : "l"(p));
    return a;
}
__device__ __forceinline__ float ex2_apx(float x) {
    float y; asm("ex2.approx.f32 %0, %1;" : "=f"(y) : "f"(x)); return y;
}
__device__ __forceinline__ float rcp_apx(float x) {
    float y; asm("rcp.approx.f32 %0, %1;" : "=f"(y) : "f"(x)); return y;
}
__device__ __forceinline__ float tanh_fast(float x) {
    float e = ex2_apx(x * 2.8853900817779268f);       // e^{2x}
    return fmaf(-2.0f, rcp_apx(1.0f + e), 1.0f);
}
__device__ __forceinline__ float sigmoid_fast(float z) {
    return rcp_apx(1.0f + ex2_apx(z * -1.4426950408889634f));
}
__device__ __forceinline__ uint32_t pkh(half a, half b) {
    return (uint32_t)__half_as_ushort(a) | ((uint32_t)__half_as_ushort(b) << 16);
}
__device__ __forceinline__ void grp_bar(int g) {
    asm volatile("bar.sync %0, %1;" :: "r"(g + 1), "r"(256) : "memory");
}

__device__ __forceinline__ void ldsm4(uint32_t r[4], uint32_t addr) {
    asm volatile("ldmatrix.sync.aligned.m8n8.x4.shared.b16 {%0,%1,%2,%3}, [%4];"
                 : "=r"(r[0]), "=r"(r[1]), "=r"(r[2]), "=r"(r[3]) : "r"(addr));
}
__device__ __forceinline__ void mma16816(float c[4], const uint32_t a[4],
                                         uint32_t b0, uint32_t b1) {
    asm volatile("mma.sync.aligned.m16n8k16.row.col.f32.f16.f16.f32 "
                 "{%0,%1,%2,%3}, {%4,%5,%6,%7}, {%8,%9}, {%0,%1,%2,%3};"
                 : "+f"(c[0]), "+f"(c[1]), "+f"(c[2]), "+f"(c[3])
                 : "r"(a[0]), "r"(a[1]), "r"(a[2]), "r"(a[3]), "r"(b0), "r"(b1));
}

// One layer: c[f][0..3] += A @ W^T, pure fp16 operands, fp32 accumulate.
// s2-outer / f-inner keeps same-acc spacing at 4 (breaks RAW chains).
template<int KS, int BROWB>
__device__ __forceinline__ void layer_mma(uint32_t aHb, uint32_t bHb,
                                          int axor, int l7, int lg, int g3,
                                          float c[4][4])
{
    #pragma unroll
    for (int s2 = 0; s2 < KS / 2; s2++) {
        uint32_t oa0 = ((uint32_t)((4 * s2 + lg) ^ axor)) << 4;
        uint32_t oa1 = ((uint32_t)((4 * s2 + 2 + lg) ^ axor)) << 4;
        uint32_t a0[4], a1[4];
        ldsm4(a0, aHb + oa0);
        ldsm4(a1, aHb + oa1);
        uint32_t ob = ((uint32_t)((4 * s2 + g3) ^ l7)) << 4;
        uint32_t bh[4][4];
        #pragma unroll
        for (int f = 0; f < 4; f++) ldsm4(bh[f], bHb + f * 8 * BROWB + ob);
        #pragma unroll
        for (int f = 0; f < 4; f++) mma16816(c[f], a0, bh[f][0], bh[f][1]);
        #pragma unroll
        for (int f = 0; f < 4; f++) mma16816(c[f], a1, bh[f][2], bh[f][3]);
    }
}

// tanh(c + b) -> fp16 into group's AHo (256B rows, swizzled)
__device__ __forceinline__ void epi_store(char* smem, float c[4][4], int bOff,
                                          int aHg, int wm, int wn, int lane)
{
    int r  = 16 * wm + (lane >> 2);        // row within 32-edge group tile
    int cl = 2 * (lane & 3);
    #pragma unroll
    for (int f = 0; f < 4; f++) {
        int col = 32 * wn + 8 * f + cl;
        float2 b = *(const float2*)(smem + bOff + col * 4);
        float t0 = tanh_fast(c[f][0] + b.x), t1 = tanh_fast(c[f][1] + b.y);
        float t2 = tanh_fast(c[f][2] + b.x), t3 = tanh_fast(c[f][3] + b.y);
        uint32_t hp01 = pkh(__float2half_rn(t0), __float2half_rn(t1));
        uint32_t hp23 = pkh(__float2half_rn(t2), __float2half_rn(t3));
        int ch = 4 * wn + f;
        int o1 = r * 256 + ((ch ^ (r & 7)) << 4) + cl * 2;
        int o2 = (r + 8) * 256 + ((ch ^ ((r + 8) & 7)) << 4) + cl * 2;
        *(uint32_t*)(smem + aHg + o1) = hp01;
        *(uint32_t*)(smem + aHg + o2) = hp23;
    }
}

// weights: plain fp16, SW-swizzled rows
__device__ __forceinline__ void wstore(char* smem, int bH, int rowB,
                                       int j, int k, float v)
{
    int off = j * rowB + ((((k >> 3) ^ (j & 7))) << 4) + (k & 7) * 2;
    *(half*)(smem + bH + off) = __float2half_rn(v);
}

typedef unsigned long long ull;

__global__ void __launch_bounds__(NTHREADS, 1)
gnn_mma_v6(const float* __restrict__ EA,
           const float* __restrict__ W1, const float* __restrict__ b1,
           const float* __restrict__ W2, const float* __restrict__ b2,
           const float* __restrict__ W3, const float* __restrict__ b3,
           const float* __restrict__ W4, const float* __restrict__ b4,
           float* __restrict__ out, int E)
{
    extern __shared__ char smem[];
    const uint32_t sb = smem_u32(smem);
    const int tid  = threadIdx.x;
    const int lane = tid & 31;
    const int warp = tid >> 5;
    const int g    = warp >> 3;            // group 0/1
    const int gw   = warp & 7;             // warp within group
    const int wm   = gw & 1, wn = gw >> 1; // 2(M) x 4(N) warp grid
    const int l7 = lane & 7, g3 = lane >> 3, lg = lane >> 4;
    const int rowA = 16 * wm + (lane & 15);
    const int axor = rowA & 7;
    const int tidg = tid & 255;            // thread within group

    // group-local buffer bases
    const int a1Hg = A1H + g * 4096;
    const int aHg  = AHo + g * 8192;

    // per-thread ldsm base addresses
    const uint32_t a1H = sb + a1Hg + rowA * 128;
    const uint32_t aH  = sb + aHg  + rowA * 256;
    const uint32_t w1H = sb + W1H + (32 * wn + l7) * 128;
    const uint32_t w2H = sb + W2H + (32 * wn + l7) * 256;
    const uint32_t w3H = sb + W3H + (32 * wn + l7) * 256;

    // ---- one-time weight store into smem (whole CTA) ----
    for (int i = tid; i < 128 * 64; i += NTHREADS)
        wstore(smem, W1H, 128, i >> 6, i & 63, W1[i]);
    for (int i = tid; i < 128 * 128; i += NTHREADS) {
        int j = i >> 7, k = i & 127;
        wstore(smem, W2H, 256, j, k, W2[i]);
        wstore(smem, W3H, 256, j, k, W3[i]);
    }
    for (int i = tid; i < 128; i += NTHREADS) {
        *(float*)(smem + B1F + i * 4) = b1[i];
        *(float*)(smem + B2F + i * 4) = b2[i];
        *(float*)(smem + B3F + i * 4) = b3[i];
        *(float*)(smem + W4F + i * 4) = W4[i];
    }
    if (tid == 0) *(float*)(smem + B4F) = b4[0];
    __syncthreads();
    const float b4s = *(const float*)(smem + B4F);

    const int NT = (E + GT - 1) >> 5;      // 32-edge tiles

    // staging map (group-local): 32 rows x 16 float4-cols, 2 cells/thread
    const int se0 = tidg >> 4, se1 = 16 + se0, sc = tidg & 15;
    const int o0 = se0 * 128 + (((sc >> 1) ^ (se0 & 7)) << 4) + (sc & 1) * 8;
    const int o1 = se1 * 128 + (((sc >> 1) ^ (se1 & 7)) << 4) + (sc & 1) * 8;

    int t = blockIdx.x * 2 + g;
    float4 v0 = make_float4(0.f, 0.f, 0.f, 0.f), v1 = v0;
    if (t < NT) {
        const float4* gp = (const float4*)(EA + ((size_t)(t * GT) << 6));
        int tb = t * GT;
        if (tb + se0 < E) v0 = __ldg(gp + se0 * 16 + sc);
        if (tb + se1 < E) v1 = __ldg(gp + se1 * 16 + sc);
    }

    // stage first tile (fp16, swizzled)
    {
        float4 vv[2] = {v0, v1};
        int oo[2] = {o0, o1};
        #pragma unroll
        for (int q = 0; q < 2; q++) {
            float4 v = vv[q];
            ull hi = (ull)pkh(__float2half_rn(v.x), __float2half_rn(v.y))
                   | ((ull)pkh(__float2half_rn(v.z), __float2half_rn(v.w)) << 32);
            *(ull*)(smem + a1Hg + oo[q]) = hi;
        }
    }
    grp_bar(g);

    // ---- PHASE STAGGER: group 1 runs an idempotent L1+epi1 / L2+epi2
    // warm-up on its first tile (all writes warp-partitioned, rewritten
    // identically by the main loop).
    if (g == 1 && t < NT) {
        float c[4][4];
        #pragma unroll
        for (int f = 0; f < 4; f++) { c[f][0]=c[f][1]=c[f][2]=c[f][3]=0.f; }
        layer_mma<4, 128>(a1H, w1H, axor, l7, lg, g3, c);
        epi_store(smem, c, B1F, aHg, wm, wn, lane);
        grp_bar(g);
        #pragma unroll
        for (int f = 0; f < 4; f++) { c[f][0]=c[f][1]=c[f][2]=c[f][3]=0.f; }
        layer_mma<8, 256>(aH, w2H, axor, l7, lg, g3, c);
        grp_bar(g);
        epi_store(smem, c, B2F, aHg, wm, wn, lane);
        grp_bar(g);
    }

    for (; t < NT; t += gridDim.x * 2) {
        const int tbase = t * GT;

        // prefetch next tile (hidden behind whole tile body)
        int tn = t + gridDim.x * 2;
        if (tn < NT) {
            const float4* gp = (const float4*)(EA + ((size_t)(tn * GT) << 6));
            int tb = tn * GT;
            v0 = (tb + se0 < E) ? __ldg(gp + se0 * 16 + sc) : make_float4(0.f,0.f,0.f,0.f);
            v1 = (tb + se1 < E) ? __ldg(gp + se1 * 16 + sc) : make_float4(0.f,0.f,0.f,0.f);
        } else {
            v0 = make_float4(0.f,0.f,0.f,0.f); v1 = v0;
        }

        float c[4][4];

        // ---- layer 1 (K=64) ----
        #pragma unroll
        for (int f = 0; f < 4; f++) { c[f][0]=c[f][1]=c[f][2]=c[f][3]=0.f; }
        layer_mma<4, 128>(a1H, w1H, axor, l7, lg, g3, c);
        epi_store(smem, c, B1F, aHg, wm, wn, lane);
        grp_bar(g);

        // ---- layer 2 (K=128) ----
        #pragma unroll
        for (int f = 0; f < 4; f++) { c[f][0]=c[f][1]=c[f][2]=c[f][3]=0.f; }
        layer_mma<8, 256>(aH, w2H, axor, l7, lg, g3, c);
        grp_bar(g);                    // WAR: epi2 overwrites AHo
        epi_store(smem, c, B2F, aHg, wm, wn, lane);
        grp_bar(g);

        // ---- layer 3 (K=128) ----
        #pragma unroll
        for (int f = 0; f < 4; f++) { c[f][0]=c[f][1]=c[f][2]=c[f][3]=0.f; }
        layer_mma<8, 256>(aH, w3H, axor, l7, lg, g3, c);

        // ---- head: tanh, dot W4, reduce ----
        {
            int r  = 16 * wm + (lane >> 2);
            int cl = 2 * (lane & 3);
            float p = 0.f, p8 = 0.f;
            #pragma unroll
            for (int f = 0; f < 4; f++) {
                int col = 32 * wn + 8 * f + cl;
                float2 b3v = *(const float2*)(smem + B3F + col * 4);
                float2 w4v = *(const float2*)(smem + W4F + col * 4);
                float t0 = tanh_fast(c[f][0] + b3v.x), t1 = tanh_fast(c[f][1] + b3v.y);
                float t2 = tanh_fast(c[f][2] + b3v.x), t3 = tanh_fast(c[f][3] + b3v.y);
                p  = fmaf(w4v.x, t0, fmaf(w4v.y, t1, p));
                p8 = fmaf(w4v.x, t2, fmaf(w4v.y, t3, p8));
            }
            p  += __shfl_xor_sync(0xFFFFFFFFu, p, 1);
            p  += __shfl_xor_sync(0xFFFFFFFFu, p, 2);
            p8 += __shfl_xor_sync(0xFFFFFFFFu, p8, 1);
            p8 += __shfl_xor_sync(0xFFFFFFFFu, p8, 2);
            if ((lane & 3) == 0) {
                *(float*)(smem + PPF + ((g * 32 + r) * 4 + wn) * 4)     = p;
                *(float*)(smem + PPF + ((g * 32 + r + 8) * 4 + wn) * 4) = p8;
            }
        }
        grp_bar(g);

        // ---- out-write + next-tile staging share one barrier window ----
        if (tidg < GT) {
            int eg = tbase + tidg;
            if (eg < E) {
                float4 pp = *(const float4*)(smem + PPF + (g * 32 + tidg) * 16);
                out[eg] = sigmoid_fast(pp.x + pp.y + pp.z + pp.w + b4s);
            }
        }
        {
            float4 vv[2] = {v0, v1};
            int oo[2] = {o0, o1};
            #pragma unroll
            for (int q = 0; q < 2; q++) {
                float4 v = vv[q];
                ull hi = (ull)pkh(__float2half_rn(v.x), __float2half_rn(v.y))
                       | ((ull)pkh(__float2half_rn(v.z), __float2half_rn(v.w)) << 32);
                *(ull*)(smem + a1Hg + oo[q]) = hi;
            }
        }
        grp_bar(g);
    }
}

extern "C" void kernel_launch(void* const* d_in, const int* in_sizes, int n_in,
                              void* d_out, int out_size)
{
    // metadata order: x, edge_index, edge_attr, W1, b1, W2, b2, W3, b3, W4, b4
    const float* EA = (const float*)d_in[2];
    const float* W1 = (const float*)d_in[3];
    const float* b1 = (const float*)d_in[4];
    const float* W2 = (const float*)d_in[5];
    const float* b2 = (const float*)d_in[6];
    const float* W3 = (const float*)d_in[7];
    const float* b3 = (const float*)d_in[8];
    const float* W4 = (const float*)d_in[9];
    const float* b4 = (const float*)d_in[10];
    float* out = (float*)d_out;
    const int E = out_size;   // 800000

    cudaFuncSetAttribute(gnn_mma_v6,
                         cudaFuncAttributeMaxDynamicSharedMemorySize, SMEM_BYTES);
    int nsm = 148;
    cudaDeviceGetAttribute(&nsm, cudaDevAttrMultiProcessorCount, 0);

    gnn_mma_v6<<<nsm, NTHREADS, SMEM_BYTES>>>(
        EA, W1, b1, W2, b2, W3, b3, W4, b4, out, E);
}

// round 17
// speedup vs baseline: 10.0610x; 1.0118x over previous
#include <cuda_runtime.h>
#include <cuda_fp16.h>
#include <cstdint>

#define NTHREADS 512
#define TE 128           // edges per CTA tile

// ---- dynamic smem byte offsets ----
#define A1B 0            // 128 x 128B fp16 input (K=64), XOR-swizzled
#define AHB 16384        // 128 x 256B fp16 activations
#define W1B 49152        // W1 [j=128][k=64] fp16, 128B rows (16KB)
#define W2B 65536        // W2 [128][128] fp16, 256B rows (32KB)
#define W3B 98304        // (32KB)
#define B1F 131072       // f32 biases etc
#define B2F 131584
#define B3F 132096
#define W4F 132608
#define B4F 133120
#define PPF 133136       // 128 x 4 f32 partials (2KB)
#define SMEM_BYTES 135680

// ======================= helpers =======================
__device__ __forceinline__ uint32_t smem_u32(const void* p) {
    uint32_t a;
    asm("{ .reg .u64 t; cvta.to.shared.u64 t, %1; cvt.u32.u64 %0, t; }"
        : "=r"(a) : "l"(p));
    return a;
}
__device__ __forceinline__ float ex2_apx(float x) {
    float y; asm("ex2.approx.f32 %0, %1;" : "=f"(y) : "f"(x)); return y;
}
__device__ __forceinline__ float rcp_apx(float x) {
    float y; asm("rcp.approx.f32 %0, %1;" : "=f"(y) : "f"(x)); return y;
}
__device__ __forceinline__ float tanh_fast(float x) {
    float e = ex2_apx(x * 2.8853900817779268f);       // e^{2x}
    return fmaf(-2.0f, rcp_apx(1.0f + e), 1.0f);
}
__device__ __forceinline__ float sigmoid_fast(float z) {
    return rcp_apx(1.0f + ex2_apx(z * -1.4426950408889634f));
}
__device__ __forceinline__ uint32_t pkh(half a, half b) {
    return (uint32_t)__half_as_ushort(a) | ((uint32_t)__half_as_ushort(b) << 16);
}

__device__ __forceinline__ void ldsm4(uint32_t r[4], uint32_t addr) {
    asm volatile("ldmatrix.sync.aligned.m8n8.x4.shared.b16 {%0,%1,%2,%3}, [%4];"
                 : "=r"(r[0]), "=r"(r[1]), "=r"(r[2]), "=r"(r[3]) : "r"(addr));
}
__device__ __forceinline__ void mma16816(float c[4], const uint32_t a[4],
                                         uint32_t b0, uint32_t b1) {
    asm volatile("mma.sync.aligned.m16n8k16.row.col.f32.f16.f16.f32 "
                 "{%0,%1,%2,%3}, {%4,%5,%6,%7}, {%8,%9}, {%0,%1,%2,%3};"
                 : "+f"(c[0]), "+f"(c[1]), "+f"(c[2]), "+f"(c[3])
                 : "r"(a[0]), "r"(a[1]), "r"(a[2]), "r"(a[3]), "r"(b0), "r"(b1));
}

// One layer, warp tile m32n32: c0 = rows [r, r+16), c1 = rows [r+16, r+32).
// Per s2 (k32): 8 ldsm4 / 16 MMA (vs 6/8 for m16n32) — 33% less smem traffic
// per MMA. Same-accumulator spacing >= 6 instructions.
template<int KS, int AROWB, int BROWB>
__device__ __forceinline__ void layer_mma(uint32_t aB, uint32_t bB,
                                          int axor, int l7, int lg, int g3,
                                          float c0[4][4], float c1[4][4])
{
    #pragma unroll
    for (int s2 = 0; s2 < KS / 2; s2++) {
        uint32_t oa0 = ((uint32_t)((4 * s2 + lg) ^ axor)) << 4;
        uint32_t oa1 = ((uint32_t)((4 * s2 + 2 + lg) ^ axor)) << 4;
        uint32_t a00[4], a01[4];
        ldsm4(a00, aB + oa0);
        ldsm4(a01, aB + 16 * AROWB + oa0);
        uint32_t ob = ((uint32_t)((4 * s2 + g3) ^ l7)) << 4;
        uint32_t bh[4][4];
        #pragma unroll
        for (int f = 0; f < 4; f++) ldsm4(bh[f], bB + f * 8 * BROWB + ob);
        #pragma unroll
        for (int f = 0; f < 4; f++) mma16816(c0[f], a00, bh[f][0], bh[f][1]);
        #pragma unroll
        for (int f = 0; f < 4; f++) mma16816(c1[f], a01, bh[f][0], bh[f][1]);
        uint32_t a10[4], a11[4];
        ldsm4(a10, aB + oa1);
        ldsm4(a11, aB + 16 * AROWB + oa1);
        #pragma unroll
        for (int f = 0; f < 4; f++) mma16816(c0[f], a10, bh[f][2], bh[f][3]);
        #pragma unroll
        for (int f = 0; f < 4; f++) mma16816(c1[f], a11, bh[f][2], bh[f][3]);
    }
}

// tanh(c + b) -> fp16 into AHB (256B rows, swizzled). Rows r,r+8 (c0), r+16,r+24 (c1).
__device__ __forceinline__ void epi_store(char* smem, float c0[4][4], float c1[4][4],
                                          int bOff, int wm, int wn, int lane)
{
    int r  = 32 * wm + (lane >> 2);
    int cl = 2 * (lane & 3);
    #pragma unroll
    for (int f = 0; f < 4; f++) {
        int col = 32 * wn + 8 * f + cl;
        float2 b = *(const float2*)(smem + bOff + col * 4);
        float t0 = tanh_fast(c0[f][0] + b.x), t1 = tanh_fast(c0[f][1] + b.y);
        float t2 = tanh_fast(c0[f][2] + b.x), t3 = tanh_fast(c0[f][3] + b.y);
        float t4 = tanh_fast(c1[f][0] + b.x), t5 = tanh_fast(c1[f][1] + b.y);
        float t6 = tanh_fast(c1[f][2] + b.x), t7 = tanh_fast(c1[f][3] + b.y);
        int ch = 4 * wn + f;
        int r8 = r + 8, r16 = r + 16, r24 = r + 24;
        *(uint32_t*)(smem + AHB + r   * 256 + ((ch ^ (r   & 7)) << 4) + cl * 2) = pkh(__float2half_rn(t0), __float2half_rn(t1));
        *(uint32_t*)(smem + AHB + r8  * 256 + ((ch ^ (r8  & 7)) << 4) + cl * 2) = pkh(__float2half_rn(t2), __float2half_rn(t3));
        *(uint32_t*)(smem + AHB + r16 * 256 + ((ch ^ (r16 & 7)) << 4) + cl * 2) = pkh(__float2half_rn(t4), __float2half_rn(t5));
        *(uint32_t*)(smem + AHB + r24 * 256 + ((ch ^ (r24 & 7)) << 4) + cl * 2) = pkh(__float2half_rn(t6), __float2half_rn(t7));
    }
}

// weights: plain fp16, SW-swizzled rows
__device__ __forceinline__ void wstore(char* smem, int bH, int rowB,
                                       int j, int k, float v)
{
    int off = j * rowB + ((((k >> 3) ^ (j & 7))) << 4) + (k & 7) * 2;
    *(half*)(smem + bH + off) = __float2half_rn(v);
}

typedef unsigned long long ull;

__global__ void __launch_bounds__(NTHREADS, 1)
gnn_mma_v7(const float* __restrict__ EA,
           const float* __restrict__ W1, const float* __restrict__ b1,
           const float* __restrict__ W2, const float* __restrict__ b2,
           const float* __restrict__ W3, const float* __restrict__ b3,
           const float* __restrict__ W4, const float* __restrict__ b4,
           float* __restrict__ out, int E)
{
    extern __shared__ char smem[];
    const uint32_t sb = smem_u32(smem);
    const int tid  = threadIdx.x;
    const int lane = tid & 31;
    const int warp = tid >> 5;
    const int wm   = warp & 3, wn = warp >> 2; // 4(M) x 4(N) warp grid
    const int l7 = lane & 7, g3 = lane >> 3, lg = lane >> 4;
    const int rowA = 32 * wm + (lane & 15);
    const int axor = rowA & 7;

    // per-thread ldsm base addresses
    const uint32_t a1B = sb + A1B + rowA * 128;
    const uint32_t aB  = sb + AHB + rowA * 256;
    const uint32_t w1  = sb + W1B + (32 * wn + l7) * 128;
    const uint32_t w2  = sb + W2B + (32 * wn + l7) * 256;
    const uint32_t w3  = sb + W3B + (32 * wn + l7) * 256;

    // ---- one-time weight store into smem ----
    for (int i = tid; i < 128 * 64; i += NTHREADS)
        wstore(smem, W1B, 128, i >> 6, i & 63, W1[i]);
    for (int i = tid; i < 128 * 128; i += NTHREADS) {
        int j = i >> 7, k = i & 127;
        wstore(smem, W2B, 256, j, k, W2[i]);
        wstore(smem, W3B, 256, j, k, W3[i]);
    }
    for (int i = tid; i < 128; i += NTHREADS) {
        *(float*)(smem + B1F + i * 4) = b1[i];
        *(float*)(smem + B2F + i * 4) = b2[i];
        *(float*)(smem + B3F + i * 4) = b3[i];
        *(float*)(smem + W4F + i * 4) = W4[i];
    }
    if (tid == 0) *(float*)(smem + B4F) = b4[0];
    __syncthreads();
    const float b4s = *(const float*)(smem + B4F);

    const int NT = (E + TE - 1) / TE;

    // staging map: 128 rows x 16 float4 cols, 4 cells/thread (rows se+32q)
    const int se = tid >> 4, sc = tid & 15;
    const int oS = se * 128 + (((sc >> 1) ^ (se & 7)) << 4) + (sc & 1) * 8;

    int t = blockIdx.x;
    ull u[4];
    #pragma unroll
    for (int q = 0; q < 4; q++) u[q] = 0ull;
    if (t < NT) {
        const float4* gp = (const float4*)(EA + ((size_t)(t * TE) << 6));
        int tb = t * TE;
        #pragma unroll
        for (int q = 0; q < 4; q++) {
            int e = se + 32 * q;
            if (tb + e < E) {
                float4 v = __ldg(gp + e * 16 + sc);
                u[q] = (ull)pkh(__float2half_rn(v.x), __float2half_rn(v.y))
                     | ((ull)pkh(__float2half_rn(v.z), __float2half_rn(v.w)) << 32);
            }
        }
    }
    // stage first tile
    #pragma unroll
    for (int q = 0; q < 4; q++)
        *(ull*)(smem + A1B + oS + 4096 * q) = u[q];
    __syncthreads();

    for (; t < NT; t += gridDim.x) {
        const int tbase = t * TE;

        // prefetch next tile (hidden behind whole tile body)
        int tn = t + gridDim.x;
        #pragma unroll
        for (int q = 0; q < 4; q++) u[q] = 0ull;
        if (tn < NT) {
            const float4* gp = (const float4*)(EA + ((size_t)(tn * TE) << 6));
            int tb = tn * TE;
            #pragma unroll
            for (int q = 0; q < 4; q++) {
                int e = se + 32 * q;
                if (tb + e < E) {
                    float4 v = __ldg(gp + e * 16 + sc);
                    u[q] = (ull)pkh(__float2half_rn(v.x), __float2half_rn(v.y))
                         | ((ull)pkh(__float2half_rn(v.z), __float2half_rn(v.w)) << 32);
                }
            }
        }

        float c0[4][4], c1[4][4];

        // ---- layer 1 (K=64) ----
        #pragma unroll
        for (int f = 0; f < 4; f++)
            #pragma unroll
            for (int i = 0; i < 4; i++) { c0[f][i] = 0.f; c1[f][i] = 0.f; }
        layer_mma<4, 128, 128>(a1B, w1, axor, l7, lg, g3, c0, c1);
        epi_store(smem, c0, c1, B1F, wm, wn, lane);
        __syncthreads();

        // ---- layer 2 (K=128) ----
        #pragma unroll
        for (int f = 0; f < 4; f++)
            #pragma unroll
            for (int i = 0; i < 4; i++) { c0[f][i] = 0.f; c1[f][i] = 0.f; }
        layer_mma<8, 256, 256>(aB, w2, axor, l7, lg, g3, c0, c1);
        __syncthreads();               // WAR: epi2 overwrites AHB
        epi_store(smem, c0, c1, B2F, wm, wn, lane);
        __syncthreads();

        // ---- layer 3 (K=128) ----
        #pragma unroll
        for (int f = 0; f < 4; f++)
            #pragma unroll
            for (int i = 0; i < 4; i++) { c0[f][i] = 0.f; c1[f][i] = 0.f; }
        layer_mma<8, 256, 256>(aB, w3, axor, l7, lg, g3, c0, c1);

        // ---- head: tanh, dot W4, reduce over lane quads ----
        {
            int r  = 32 * wm + (lane >> 2);
            int cl = 2 * (lane & 3);
            float p0 = 0.f, p1 = 0.f, p2 = 0.f, p3 = 0.f;
            #pragma unroll
            for (int f = 0; f < 4; f++) {
                int col = 32 * wn + 8 * f + cl;
                float2 b3v = *(const float2*)(smem + B3F + col * 4);
                float2 w4v = *(const float2*)(smem + W4F + col * 4);
                p0 = fmaf(w4v.x, tanh_fast(c0[f][0] + b3v.x),
                     fmaf(w4v.y, tanh_fast(c0[f][1] + b3v.y), p0));
                p1 = fmaf(w4v.x, tanh_fast(c0[f][2] + b3v.x),
                     fmaf(w4v.y, tanh_fast(c0[f][3] + b3v.y), p1));
                p2 = fmaf(w4v.x, tanh_fast(c1[f][0] + b3v.x),
                     fmaf(w4v.y, tanh_fast(c1[f][1] + b3v.y), p2));
                p3 = fmaf(w4v.x, tanh_fast(c1[f][2] + b3v.x),
                     fmaf(w4v.y, tanh_fast(c1[f][3] + b3v.y), p3));
            }
            p0 += __shfl_xor_sync(0xFFFFFFFFu, p0, 1);
            p0 += __shfl_xor_sync(0xFFFFFFFFu, p0, 2);
            p1 += __shfl_xor_sync(0xFFFFFFFFu, p1, 1);
            p1 += __shfl_xor_sync(0xFFFFFFFFu, p1, 2);
            p2 += __shfl_xor_sync(0xFFFFFFFFu, p2, 1);
            p2 += __shfl_xor_sync(0xFFFFFFFFu, p2, 2);
            p3 += __shfl_xor_sync(0xFFFFFFFFu, p3, 1);
            p3 += __shfl_xor_sync(0xFFFFFFFFu, p3, 2);
            if ((lane & 3) == 0) {
                *(float*)(smem + PPF + ((r)      * 4 + wn) * 4) = p0;
                *(float*)(smem + PPF + ((r + 8)  * 4 + wn) * 4) = p1;
                *(float*)(smem + PPF + ((r + 16) * 4 + wn) * 4) = p2;
                *(float*)(smem + PPF + ((r + 24) * 4 + wn) * 4) = p3;
            }
        }
        __syncthreads();

        // ---- out-write + next-tile staging share one barrier window ----
        if (tid < TE) {
            int eg = tbase + tid;
            if (eg < E) {
                float4 pp = *(const float4*)(smem + PPF + tid * 16);
                out[eg] = sigmoid_fast(pp.x + pp.y + pp.z + pp.w + b4s);
            }
        }
        #pragma unroll
        for (int q = 0; q < 4; q++)
            *(ull*)(smem + A1B + oS + 4096 * q) = u[q];
        __syncthreads();
    }
}

extern "C" void kernel_launch(void* const* d_in, const int* in_sizes, int n_in,
                              void* d_out, int out_size)
{
    // metadata order: x, edge_index, edge_attr, W1, b1, W2, b2, W3, b3, W4, b4
    const float* EA = (const float*)d_in[2];
    const float* W1 = (const float*)d_in[3];
    const float* b1 = (const float*)d_in[4];
    const float* W2 = (const float*)d_in[5];
    const float* b2 = (const float*)d_in[6];
    const float* W3 = (const float*)d_in[7];
    const float* b3 = (const float*)d_in[8];
    const float* W4 = (const float*)d_in[9];
    const float* b4 = (const float*)d_in[10];
    float* out = (float*)d_out;
    const int E = out_size;   // 800000

    cudaFuncSetAttribute(gnn_mma_v7,
                         cudaFuncAttributeMaxDynamicSharedMemorySize, SMEM_BYTES);
    int nsm = 148;
    cudaDeviceGetAttribute(&nsm, cudaDevAttrMultiProcessorCount, 0);

    gnn_mma_v7<<<nsm, NTHREADS, SMEM_BYTES>>>(
        EA, W1, b1, W2, b2, W3, b3, W4, b4, out, E);
}